// round 7
// baseline (speedup 1.0000x reference)
#include <cuda_runtime.h>
#include <cuda_bf16.h>
#include <cstdint>

#define BN   32
#define SEQ  577
#define CH   768
#define NH   12
#define DH   64
#define MROWS (BN*SEQ)      /* 18464 */
#define QKV_N (3*CH)        /* 2304  */
#define QT   128
#define KT   128
#define NKT  5              /* ceil(577/128) */

// ---------------- scratch (__device__ globals; no allocs allowed) ----------
__device__ __nv_bfloat16 g_qh[BN*NH*SEQ*DH], g_ql[BN*NH*SEQ*DH];
__device__ __nv_bfloat16 g_kh[BN*NH*SEQ*DH], g_kl[BN*NH*SEQ*DH];
__device__ __nv_bfloat16 g_vh[BN*NH*SEQ*DH], g_vl[BN*NH*SEQ*DH];
__device__ __nv_bfloat16 g_xh[MROWS*CH], g_xl[MROWS*CH];   // A hi/lo (x, then attn out)
__device__ __nv_bfloat16 g_wh[QKV_N*CH], g_wl[QKV_N*CH];   // qkv_w hi/lo
__device__ __nv_bfloat16 g_ph[CH*CH],   g_pl[CH*CH];       // proj_w hi/lo

// ---------------- helpers ---------------------------------------------------
__device__ __forceinline__ uint32_t smem_u32(const void* p) {
    uint32_t a;
    asm("{ .reg .u64 t; cvta.to.shared.u64 t, %1; cvt.u32.u64 %0, t; }" : "=r"(a) : "l"(p));
    return a;
}
__device__ __forceinline__ void ldsm_x4(uint32_t& r0, uint32_t& r1,
                                        uint32_t& r2, uint32_t& r3, uint32_t addr) {
    asm volatile("ldmatrix.sync.aligned.m8n8.x4.shared.b16 {%0,%1,%2,%3}, [%4];"
                 : "=r"(r0), "=r"(r1), "=r"(r2), "=r"(r3) : "r"(addr));
}
__device__ __forceinline__ void ldsm_x4_t(uint32_t& r0, uint32_t& r1,
                                          uint32_t& r2, uint32_t& r3, uint32_t addr) {
    asm volatile("ldmatrix.sync.aligned.m8n8.x4.trans.shared.b16 {%0,%1,%2,%3}, [%4];"
                 : "=r"(r0), "=r"(r1), "=r"(r2), "=r"(r3) : "r"(addr));
}
__device__ __forceinline__ void mma16816(float* c, const uint32_t* a, const uint32_t* b) {
    asm volatile("mma.sync.aligned.m16n8k16.row.col.f32.bf16.bf16.f32 "
                 "{%0,%1,%2,%3}, {%4,%5,%6,%7}, {%8,%9}, {%0,%1,%2,%3};"
                 : "+f"(c[0]), "+f"(c[1]), "+f"(c[2]), "+f"(c[3])
                 : "r"(a[0]), "r"(a[1]), "r"(a[2]), "r"(a[3]), "r"(b[0]), "r"(b[1]));
}
__device__ __forceinline__ void mma2(float* c, const uint32_t* a, uint32_t b0, uint32_t b1) {
    asm volatile("mma.sync.aligned.m16n8k16.row.col.f32.bf16.bf16.f32 "
                 "{%0,%1,%2,%3}, {%4,%5,%6,%7}, {%8,%9}, {%0,%1,%2,%3};"
                 : "+f"(c[0]), "+f"(c[1]), "+f"(c[2]), "+f"(c[3])
                 : "r"(a[0]), "r"(a[1]), "r"(a[2]), "r"(a[3]), "r"(b0), "r"(b1));
}
// 128B-row swizzle: row r, 16B-chunk c (0..7) — conflict-free ldmatrix
__device__ __forceinline__ uint32_t aswz(int r, int c) {
    return (uint32_t)(r * 128 + ((c ^ (r & 7)) << 4));
}
// fp32 pair -> bf16 hi pair + bf16 lo pair (packed u32)
__device__ __forceinline__ void split2(float x, float y, uint32_t& hi, uint32_t& lo) {
    __nv_bfloat162 h2 = __floats2bfloat162_rn(x, y);
    __nv_bfloat162 l2 = __floats2bfloat162_rn(x - __bfloat162float(h2.x),
                                              y - __bfloat162float(h2.y));
    hi = reinterpret_cast<uint32_t&>(h2);
    lo = reinterpret_cast<uint32_t&>(l2);
}

// ---------------- split: fp32 -> bf16 hi + bf16 lo -------------------------
__global__ void split_kernel(const float* __restrict__ src, int sel, int n) {
    int i = blockIdx.x * 256 + threadIdx.x;
    if (i >= n) return;
    float v = src[i];
    __nv_bfloat16 h = __float2bfloat16(v);
    __nv_bfloat16 l = __float2bfloat16(v - __bfloat162float(h));
    if (sel == 0)      { g_xh[i] = h; g_xl[i] = l; }
    else if (sel == 1) { g_wh[i] = h; g_wl[i] = l; }
    else               { g_ph[i] = h; g_pl[i] = l; }
}

// ---------------- mma.sync bf16x3 GEMM ---------------------------------------
// 128x128 tile, BK=64, 512 thr / 16 warps (32x32 warp tiles),
// 2-stage smem double buffer, ONE __syncthreads per K-chunk.
#define NKC 12                         /* 768 / 64 */
#define G_AH 0
#define G_AL 16384
#define G_BH 32768
#define G_BL 49152
#define G_STAGE 65536
#define G_SMEM (2*G_STAGE)             /* 131072 */

template<int MODE>
__global__ __launch_bounds__(512) void mma_gemm(const float* __restrict__ bias,
                                                float* __restrict__ out)
{
    extern __shared__ __align__(16) char smem[];
    const uint32_t sb = smem_u32(smem);
    const int tid = threadIdx.x, lane = tid & 31, wid = tid >> 5;
    const int wm = wid & 3, wn = wid >> 2;          // 4 x 4 warp grid, 32x32 tiles
    const int tileN = blockIdx.x, tileM = blockIdx.y;

    const __nv_bfloat16* __restrict__ Ah = g_xh;
    const __nv_bfloat16* __restrict__ Al = g_xl;
    const __nv_bfloat16* __restrict__ Bh = (MODE == 0) ? g_wh : g_ph;
    const __nv_bfloat16* __restrict__ Bl = (MODE == 0) ? g_wl : g_pl;

    // loader: 128 rows x 8 chunks of 16B per buffer; 512 thr -> 2 int4 each
    const int lr = tid >> 2;                 // 0..127
    const int lc = (tid & 3) << 1;           // chunks lc, lc+1
    int ga = tileM * 128 + lr; if (ga > MROWS - 1) ga = MROWS - 1;
    const int gb = tileN * 128 + lr;
    const size_t abase = (size_t)ga * CH + lc * 8;
    const size_t bbase = (size_t)gb * CH + lc * 8;
    const uint32_t so0 = aswz(lr, lc), so1 = aswz(lr, lc + 1);

    float acc[2][4][4];
    #pragma unroll
    for (int i = 0; i < 2; ++i)
        #pragma unroll
        for (int j = 0; j < 4; ++j)
            #pragma unroll
            for (int r = 0; r < 4; ++r) acc[i][j][r] = 0.f;

    int4 pah[2], pal[2], pbh[2], pbl[2];
    // chunk 0 -> regs -> stage 0
    pah[0] = *(const int4*)(Ah + abase); pah[1] = *(const int4*)(Ah + abase + 8);
    pal[0] = *(const int4*)(Al + abase); pal[1] = *(const int4*)(Al + abase + 8);
    pbh[0] = *(const int4*)(Bh + bbase); pbh[1] = *(const int4*)(Bh + bbase + 8);
    pbl[0] = *(const int4*)(Bl + bbase); pbl[1] = *(const int4*)(Bl + bbase + 8);
    {
        char* st = smem;                     // stage 0
        *(int4*)(st + G_AH + so0) = pah[0];  *(int4*)(st + G_AH + so1) = pah[1];
        *(int4*)(st + G_AL + so0) = pal[0];  *(int4*)(st + G_AL + so1) = pal[1];
        *(int4*)(st + G_BH + so0) = pbh[0];  *(int4*)(st + G_BH + so1) = pbh[1];
        *(int4*)(st + G_BL + so0) = pbl[0];  *(int4*)(st + G_BL + so1) = pbl[1];
    }
    // chunk 1 -> regs
    {
        const size_t ao = abase + 64, bo = bbase + 64;
        pah[0] = *(const int4*)(Ah + ao); pah[1] = *(const int4*)(Ah + ao + 8);
        pal[0] = *(const int4*)(Al + ao); pal[1] = *(const int4*)(Al + ao + 8);
        pbh[0] = *(const int4*)(Bh + bo); pbh[1] = *(const int4*)(Bh + bo + 8);
        pbl[0] = *(const int4*)(Bl + bo); pbl[1] = *(const int4*)(Bl + bo + 8);
    }

    for (int kc = 0; kc < NKC; ++kc) {
        // ONE barrier: drains prior STS (stage kc&1 now complete) and
        // guarantees everyone finished reading stage (kc+1)&1 in iter kc-1.
        __syncthreads();

        if (kc + 1 < NKC) {                  // store chunk kc+1 -> other stage
            char* st = smem + ((kc + 1) & 1) * G_STAGE;
            *(int4*)(st + G_AH + so0) = pah[0];  *(int4*)(st + G_AH + so1) = pah[1];
            *(int4*)(st + G_AL + so0) = pal[0];  *(int4*)(st + G_AL + so1) = pal[1];
            *(int4*)(st + G_BH + so0) = pbh[0];  *(int4*)(st + G_BH + so1) = pbh[1];
            *(int4*)(st + G_BL + so0) = pbl[0];  *(int4*)(st + G_BL + so1) = pbl[1];
        }
        if (kc + 2 < NKC) {                  // prefetch chunk kc+2 -> regs
            const size_t ao = abase + (size_t)(kc + 2) * 64;
            const size_t bo = bbase + (size_t)(kc + 2) * 64;
            pah[0] = *(const int4*)(Ah + ao); pah[1] = *(const int4*)(Ah + ao + 8);
            pal[0] = *(const int4*)(Al + ao); pal[1] = *(const int4*)(Al + ao + 8);
            pbh[0] = *(const int4*)(Bh + bo); pbh[1] = *(const int4*)(Bh + bo + 8);
            pbl[0] = *(const int4*)(Bl + bo); pbl[1] = *(const int4*)(Bl + bo + 8);
        }

        const uint32_t st = sb + (kc & 1) * G_STAGE;
        #pragma unroll
        for (int k16 = 0; k16 < 4; ++k16) {
            uint32_t ah[2][4], al[2][4];
            #pragma unroll
            for (int mf = 0; mf < 2; ++mf) {
                int row = wm * 32 + mf * 16 + (lane & 15);
                int c   = 2 * k16 + (lane >> 4);
                uint32_t o = aswz(row, c);
                ldsm_x4(ah[mf][0], ah[mf][1], ah[mf][2], ah[mf][3], st + G_AH + o);
                ldsm_x4(al[mf][0], al[mf][1], al[mf][2], al[mf][3], st + G_AL + o);
            }
            uint32_t bh[4][2], bl[4][2];
            #pragma unroll
            for (int np = 0; np < 2; ++np) {
                int g = lane >> 3, l = lane & 7;
                int row = wn * 32 + np * 16 + (g >> 1) * 8 + l;
                int c   = 2 * k16 + (g & 1);
                uint32_t o = aswz(row, c);
                ldsm_x4(bh[np*2][0], bh[np*2][1], bh[np*2+1][0], bh[np*2+1][1],
                        st + G_BH + o);
                ldsm_x4(bl[np*2][0], bl[np*2][1], bl[np*2+1][0], bl[np*2+1][1],
                        st + G_BL + o);
            }
            #pragma unroll
            for (int mf = 0; mf < 2; ++mf)
                #pragma unroll
                for (int nf = 0; nf < 4; ++nf) {
                    mma16816(acc[mf][nf], ah[mf], bh[nf]);
                    mma16816(acc[mf][nf], ah[mf], bl[nf]);
                    mma16816(acc[mf][nf], al[mf], bh[nf]);
                }
        }
    }

    // ---------------- epilogue ----------------
    const int s = (MODE == 0) ? (tileN * 128) / CH : 0;
    const float scl = (MODE == 0 && s == 0) ? 0.125f : 1.0f;

    #pragma unroll
    for (int mf = 0; mf < 2; ++mf) {
        const int rbase = tileM * 128 + wm * 32 + mf * 16 + (lane >> 2);
        #pragma unroll
        for (int nf = 0; nf < 4; ++nf) {
            const int gcol = tileN * 128 + wn * 32 + nf * 8 + ((lane & 3) << 1);
            const float b0 = bias[gcol], b1 = bias[gcol + 1];
            #pragma unroll
            for (int hh = 0; hh < 2; ++hh) {
                const int row = rbase + hh * 8;
                if (row >= MROWS) continue;
                float v0 = (acc[mf][nf][hh*2+0] + b0) * scl;
                float v1 = (acc[mf][nf][hh*2+1] + b1) * scl;
                if (MODE == 0) {
                    int rem = gcol - s * CH;
                    int hd = rem >> 6, d = rem & 63;
                    int bb = row / SEQ, n = row - bb * SEQ;
                    size_t di = ((size_t)(bb * NH + hd) * SEQ + n) * DH + d;
                    __nv_bfloat16 *dsth, *dstl;
                    if (s == 0)      { dsth = g_qh; dstl = g_ql; }
                    else if (s == 1) { dsth = g_kh; dstl = g_kl; }
                    else             { dsth = g_vh; dstl = g_vl; }
                    uint32_t hp, lp;
                    split2(v0, v1, hp, lp);
                    *(uint32_t*)(dsth + di) = hp;
                    *(uint32_t*)(dstl + di) = lp;
                } else {
                    *(float2*)(out + (size_t)row * CH + gcol) = make_float2(v0, v1);
                }
            }
        }
    }
}

// ---------------- mma.sync flash attention (R4/R6 version) ------------------
#define ATT_QH 0
#define ATT_QL 16384
#define ATT_KH 32768
#define ATT_KL 49152
#define ATT_VH 65536
#define ATT_VL 81920
#define ATT_SMEM 98304

__global__ __launch_bounds__(256) void attn_mma()
{
    extern __shared__ char sm[];
    const uint32_t sb = smem_u32(sm);
    const int tid = threadIdx.x, lane = tid & 31, w = tid >> 5;
    const int q0 = blockIdx.x * QT;
    const int hh = blockIdx.y, b = blockIdx.z;
    const size_t hb = (size_t)(b * NH + hh) * SEQ;

    // load Q tile (hi/lo), swizzled
    #pragma unroll
    for (int p = 0; p < 4; ++p) {
        int slot = tid + p * 256;
        int r = slot >> 3, c = slot & 7;
        int gr = q0 + r; if (gr > SEQ - 1) gr = SEQ - 1;
        size_t idx = ((hb + gr) << 6) + c * 8;
        uint32_t so = aswz(r, c);
        *(int4*)(sm + ATT_QH + so) = *(const int4*)(g_qh + idx);
        *(int4*)(sm + ATT_QL + so) = *(const int4*)(g_ql + idx);
    }
    __syncthreads();

    // Q fragments in registers (4 k16 steps over DH)
    uint32_t qh[4][4], ql[4][4];
    #pragma unroll
    for (int kd = 0; kd < 4; ++kd) {
        int row = w * 16 + (lane & 15);
        int c = 2 * kd + (lane >> 4);
        uint32_t o = aswz(row, c);
        ldsm_x4(qh[kd][0], qh[kd][1], qh[kd][2], qh[kd][3], sb + ATT_QH + o);
        ldsm_x4(ql[kd][0], ql[kd][1], ql[kd][2], ql[kd][3], sb + ATT_QL + o);
    }

    float o[8][4];
    #pragma unroll
    for (int i = 0; i < 8; ++i)
        #pragma unroll
        for (int j = 0; j < 4; ++j) o[i][j] = 0.f;
    float m0 = -1e30f, m1 = -1e30f, l0 = 0.f, l1 = 0.f;

    for (int kt = 0; kt < NKT; ++kt) {
        const int k0 = kt * KT;
        __syncthreads();
        #pragma unroll
        for (int p = 0; p < 4; ++p) {
            int slot = tid + p * 256;
            int r = slot >> 3, c = slot & 7;
            int gk = k0 + r; if (gk > SEQ - 1) gk = SEQ - 1;
            size_t idx = ((hb + gk) << 6) + c * 8;
            uint32_t so = aswz(r, c);
            *(int4*)(sm + ATT_KH + so) = *(const int4*)(g_kh + idx);
            *(int4*)(sm + ATT_KL + so) = *(const int4*)(g_kl + idx);
        *(int4*)(sm + ATT_VH + so) = *(const int4*)(g_vh + idx);
            *(int4*)(sm + ATT_VL + so) = *(const int4*)(g_vl + idx);
        }
        __syncthreads();

        // ---- S = Q K^T ----
        float s[16][4];
        #pragma unroll
        for (int i = 0; i < 16; ++i)
            #pragma unroll
            for (int j = 0; j < 4; ++j) s[i][j] = 0.f;

        #pragma unroll
        for (int kp = 0; kp < 8; ++kp) {
            #pragma unroll
            for (int kd = 0; kd < 4; ++kd) {
                int g = lane >> 3, li = lane & 7;
                int row = kp * 16 + ((g >> 1) << 3) + li;
                int c = 2 * kd + (g & 1);
                uint32_t so = aswz(row, c);
                uint32_t kh4[4], kl4[4];
                ldsm_x4(kh4[0], kh4[1], kh4[2], kh4[3], sb + ATT_KH + so);
                ldsm_x4(kl4[0], kl4[1], kl4[2], kl4[3], sb + ATT_KL + so);
                mma2(s[2*kp],   qh[kd], kh4[0], kh4[1]);
                mma2(s[2*kp],   qh[kd], kl4[0], kl4[1]);
                mma2(s[2*kp],   ql[kd], kh4[0], kh4[1]);
                mma2(s[2*kp+1], qh[kd], kh4[2], kh4[3]);
                mma2(s[2*kp+1], qh[kd], kl4[2], kl4[3]);
                mma2(s[2*kp+1], ql[kd], kh4[2], kh4[3]);
            }
        }

        // mask invalid keys (last tile)
        if (k0 + KT > SEQ) {
            #pragma unroll
            for (int kn = 0; kn < 16; ++kn) {
                int kg = k0 + kn * 8 + ((lane & 3) << 1);
                if (kg >= SEQ)     { s[kn][0] = -1e30f; s[kn][2] = -1e30f; }
                if (kg + 1 >= SEQ) { s[kn][1] = -1e30f; s[kn][3] = -1e30f; }
            }
        }

        // ---- online softmax ----
        float mx0 = -1e30f, mx1 = -1e30f;
        #pragma unroll
        for (int kn = 0; kn < 16; ++kn) {
            mx0 = fmaxf(mx0, fmaxf(s[kn][0], s[kn][1]));
            mx1 = fmaxf(mx1, fmaxf(s[kn][2], s[kn][3]));
        }
        mx0 = fmaxf(mx0, __shfl_xor_sync(0xffffffffu, mx0, 1));
        mx0 = fmaxf(mx0, __shfl_xor_sync(0xffffffffu, mx0, 2));
        mx1 = fmaxf(mx1, __shfl_xor_sync(0xffffffffu, mx1, 1));
        mx1 = fmaxf(mx1, __shfl_xor_sync(0xffffffffu, mx1, 2));
        float mn0 = fmaxf(m0, mx0), mn1 = fmaxf(m1, mx1);
        float c0 = __expf(m0 - mn0), c1 = __expf(m1 - mn1);
        float sum0 = 0.f, sum1 = 0.f;
        #pragma unroll
        for (int kn = 0; kn < 16; ++kn) {
            s[kn][0] = __expf(s[kn][0] - mn0);
            s[kn][1] = __expf(s[kn][1] - mn0);
            s[kn][2] = __expf(s[kn][2] - mn1);
            s[kn][3] = __expf(s[kn][3] - mn1);
            sum0 += s[kn][0] + s[kn][1];
            sum1 += s[kn][2] + s[kn][3];
        }
        sum0 += __shfl_xor_sync(0xffffffffu, sum0, 1);
        sum0 += __shfl_xor_sync(0xffffffffu, sum0, 2);
        sum1 += __shfl_xor_sync(0xffffffffu, sum1, 1);
        sum1 += __shfl_xor_sync(0xffffffffu, sum1, 2);
        l0 = l0 * c0 + sum0; l1 = l1 * c1 + sum1;
        m0 = mn0; m1 = mn1;
        #pragma unroll
        for (int nf = 0; nf < 8; ++nf) {
            o[nf][0] *= c0; o[nf][1] *= c0;
            o[nf][2] *= c1; o[nf][3] *= c1;
        }

        // ---- PV: O += P V  (P packed from S regs) ----
        #pragma unroll
        for (int kk = 0; kk < 8; ++kk) {
            uint32_t ah[4], al[4];
            split2(s[2*kk][0],   s[2*kk][1],   ah[0], al[0]);
            split2(s[2*kk][2],   s[2*kk][3],   ah[1], al[1]);
            split2(s[2*kk+1][0], s[2*kk+1][1], ah[2], al[2]);
            split2(s[2*kk+1][2], s[2*kk+1][3], ah[3], al[3]);
            #pragma unroll
            for (int d16 = 0; d16 < 4; ++d16) {
                int g = lane >> 3, li = lane & 7;
                int row = kk * 16 + ((g & 1) << 3) + li;
                int c = d16 * 2 + (g >> 1);
                uint32_t so = aswz(row, c);
                uint32_t vh4[4], vl4[4];
                ldsm_x4_t(vh4[0], vh4[1], vh4[2], vh4[3], sb + ATT_VH + so);
                ldsm_x4_t(vl4[0], vl4[1], vl4[2], vl4[3], sb + ATT_VL + so);
                mma2(o[2*d16],   ah, vh4[0], vh4[1]);
                mma2(o[2*d16],   al, vh4[0], vh4[1]);
                mma2(o[2*d16],   ah, vl4[0], vl4[1]);
                mma2(o[2*d16+1], ah, vh4[2], vh4[3]);
                mma2(o[2*d16+1], al, vh4[2], vh4[3]);
                mma2(o[2*d16+1], ah, vl4[2], vl4[3]);
            }
        }
    }

    // ---- epilogue: o/l -> bf16 hi/lo into proj-A buffers ----
    float r0 = 1.f / l0, r1 = 1.f / l1;
    int rg = lane >> 2, t2 = (lane & 3) << 1;
    int row0 = q0 + w * 16 + rg, row1 = row0 + 8;
    #pragma unroll
    for (int nf = 0; nf < 8; ++nf) {
        int col = hh * DH + nf * 8 + t2;
        if (row0 < SEQ) {
            size_t gi = (size_t)(b * SEQ + row0) * CH + col;
            uint32_t hp, lp;
            split2(o[nf][0] * r0, o[nf][1] * r0, hp, lp);
            *(uint32_t*)(g_xh + gi) = hp;
            *(uint32_t*)(g_xl + gi) = lp;
        }
        if (row1 < SEQ) {
            size_t gi = (size_t)(b * SEQ + row1) * CH + col;
            uint32_t hp, lp;
            split2(o[nf][2] * r1, o[nf][3] * r1, hp, lp);
            *(uint32_t*)(g_xh + gi) = hp;
            *(uint32_t*)(g_xl + gi) = lp;
        }
    }
}

// ---------------------------------------------------------------------------
extern "C" void kernel_launch(void* const* d_in, const int* in_sizes, int n_in,
                              void* d_out, int out_size)
{
    const float* x      = (const float*)d_in[0];
    const float* qkv_w  = (const float*)d_in[1];
    const float* qkv_b  = (const float*)d_in[2];
    const float* proj_w = (const float*)d_in[3];
    const float* proj_b = (const float*)d_in[4];
    float* out = (float*)d_out;

    cudaFuncSetAttribute(mma_gemm<0>, cudaFuncAttributeMaxDynamicSharedMemorySize, G_SMEM);
    cudaFuncSetAttribute(mma_gemm<1>, cudaFuncAttributeMaxDynamicSharedMemorySize, G_SMEM);
    cudaFuncSetAttribute(attn_mma, cudaFuncAttributeMaxDynamicSharedMemorySize, ATT_SMEM);

    split_kernel<<<(MROWS*CH + 255)/256, 256>>>(x, 0, MROWS*CH);
    split_kernel<<<(QKV_N*CH + 255)/256, 256>>>(qkv_w, 1, QKV_N*CH);
    split_kernel<<<(CH*CH + 255)/256, 256>>>(proj_w, 2, CH*CH);

    mma_gemm<0><<<dim3(QKV_N/128, (MROWS + 127)/128), 512, G_SMEM>>>(qkv_b, nullptr);

    attn_mma<<<dim3((SEQ + QT - 1)/QT, NH, BN), 256, ATT_SMEM>>>();

    mma_gemm<1><<<dim3(CH/128, (MROWS + 127)/128), 512, G_SMEM>>>(proj_b, out);
}

// round 8
// speedup vs baseline: 1.7203x; 1.7203x over previous
#include <cuda_runtime.h>
#include <cuda_fp16.h>
#include <cstdint>

#define BN   32
#define SEQ  577
#define CH   768
#define NH   12
#define DH   64
#define MROWS (BN*SEQ)      /* 18464 */
#define QKV_N (3*CH)        /* 2304  */
#define QT   128
#define KT   128
#define NKT  5              /* ceil(577/128) */

// ---------------- scratch (__device__ globals; no allocs allowed) ----------
__device__ __half g_qh[BN*NH*SEQ*DH], g_ql[BN*NH*SEQ*DH];   // q hi/lo (scaled)
__device__ __half g_kh[BN*NH*SEQ*DH];                        // k single fp16
__device__ __half g_vh[BN*NH*SEQ*DH];                        // v single fp16
__device__ __half g_xh[MROWS*CH], g_xl[MROWS*CH];            // A hi/lo (x, then attn out)
__device__ __half g_wh[QKV_N*CH];                            // qkv_w single fp16
__device__ __half g_ph[CH*CH];                               // proj_w single fp16

// ---------------- helpers ---------------------------------------------------
__device__ __forceinline__ uint32_t smem_u32(const void* p) {
    uint32_t a;
    asm("{ .reg .u64 t; cvta.to.shared.u64 t, %1; cvt.u32.u64 %0, t; }" : "=r"(a) : "l"(p));
    return a;
}
__device__ __forceinline__ void ldsm_x4(uint32_t& r0, uint32_t& r1,
                                        uint32_t& r2, uint32_t& r3, uint32_t addr) {
    asm volatile("ldmatrix.sync.aligned.m8n8.x4.shared.b16 {%0,%1,%2,%3}, [%4];"
                 : "=r"(r0), "=r"(r1), "=r"(r2), "=r"(r3) : "r"(addr));
}
__device__ __forceinline__ void ldsm_x4_t(uint32_t& r0, uint32_t& r1,
                                          uint32_t& r2, uint32_t& r3, uint32_t addr) {
    asm volatile("ldmatrix.sync.aligned.m8n8.x4.trans.shared.b16 {%0,%1,%2,%3}, [%4];"
                 : "=r"(r0), "=r"(r1), "=r"(r2), "=r"(r3) : "r"(addr));
}
__device__ __forceinline__ void mma16816(float* c, const uint32_t* a, const uint32_t* b) {
    asm volatile("mma.sync.aligned.m16n8k16.row.col.f32.f16.f16.f32 "
                 "{%0,%1,%2,%3}, {%4,%5,%6,%7}, {%8,%9}, {%0,%1,%2,%3};"
                 : "+f"(c[0]), "+f"(c[1]), "+f"(c[2]), "+f"(c[3])
                 : "r"(a[0]), "r"(a[1]), "r"(a[2]), "r"(a[3]), "r"(b[0]), "r"(b[1]));
}
__device__ __forceinline__ void mma2(float* c, const uint32_t* a, uint32_t b0, uint32_t b1) {
    asm volatile("mma.sync.aligned.m16n8k16.row.col.f32.f16.f16.f32 "
                 "{%0,%1,%2,%3}, {%4,%5,%6,%7}, {%8,%9}, {%0,%1,%2,%3};"
                 : "+f"(c[0]), "+f"(c[1]), "+f"(c[2]), "+f"(c[3])
                 : "r"(a[0]), "r"(a[1]), "r"(a[2]), "r"(a[3]), "r"(b0), "r"(b1));
}
// GEMM tile swizzle: 64B rows, 4 chunks
__device__ __forceinline__ uint32_t swoff(int r, int c) {
    return (uint32_t)(r * 64 + ((c ^ ((r >> 1) & 3)) << 4));
}
// attention tile swizzle: 128B rows, 8 chunks
__device__ __forceinline__ uint32_t aswz(int r, int c) {
    return (uint32_t)(r * 128 + ((c ^ (r & 7)) << 4));
}
// fp32 pair -> fp16 hi pair + fp16 lo pair (packed u32)
__device__ __forceinline__ void split2(float x, float y, uint32_t& hi, uint32_t& lo) {
    __half2 h2 = __floats2half2_rn(x, y);
    __half2 l2 = __floats2half2_rn(x - __half2float(__low2half(h2)),
                                   y - __half2float(__high2half(h2)));
    hi = reinterpret_cast<uint32_t&>(h2);
    lo = reinterpret_cast<uint32_t&>(l2);
}
__device__ __forceinline__ uint32_t pack2h(float x, float y) {
    __half2 h2 = __floats2half2_rn(x, y);
    return reinterpret_cast<uint32_t&>(h2);
}

// ---------------- split kernels ---------------------------------------------
// sel 0: x -> g_xh/g_xl (hi/lo).  sel 1: qkv_w -> g_wh.  sel 2: proj_w -> g_ph.
__global__ void split_kernel(const float* __restrict__ src, int sel, int n) {
    int i = blockIdx.x * 256 + threadIdx.x;
    if (i >= n) return;
    float v = src[i];
    __half h = __float2half_rn(v);
    if (sel == 0) {
        g_xh[i] = h;
        g_xl[i] = __float2half_rn(v - __half2float(h));
    } else if (sel == 1) {
        g_wh[i] = h;
    } else {
        g_ph[i] = h;
    }
}

// ---------------- mma.sync fp16x2 GEMM (R6 skeleton) -------------------------
// 128x128 tile, BK=32, 512 thr / 16 warps (32x32 warp tiles),
// single-stage smem + register prefetch. C = (Ah+Al)*Bh.
// MODE 0: A=x(split), B=qkv_w -> q(hi/lo, *0.125), k, v (+bias)
// MODE 1: A=attn-out(split), B=proj_w -> out (+bias)
template<int MODE>
__global__ __launch_bounds__(512) void mma_gemm(const float* __restrict__ bias,
                                                float* __restrict__ out)
{
    __shared__ __align__(16) char smem[24576];
    const uint32_t sb = smem_u32(smem);
    const int tid = threadIdx.x, lane = tid & 31, wid = tid >> 5;
    const int wm = wid & 3, wn = wid >> 2;          // 4 x 4 warp grid, 32x32 tiles
    const int tileN = blockIdx.x, tileM = blockIdx.y;

    const __half* __restrict__ Ah = g_xh;
    const __half* __restrict__ Al = g_xl;
    const __half* __restrict__ Bh = (MODE == 0) ? g_wh : g_ph;

    const uint32_t OFF_AH = 0, OFF_AL = 8192, OFF_BH = 16384;

    // loader: 512 threads, one 16B chunk per buffer (128 rows x 4 chunks)
    const int lr = tid >> 2;            // 0..127
    const int lc = tid & 3;             // 0..3
    int ga = tileM * 128 + lr; if (ga > MROWS - 1) ga = MROWS - 1;
    const int gb = tileN * 128 + lr;
    const size_t abase = (size_t)ga * CH + lc * 8;
    const size_t bbase = (size_t)gb * CH + lc * 8;
    const uint32_t so = swoff(lr, lc);

    float acc[2][4][4];
    #pragma unroll
    for (int i = 0; i < 2; ++i)
        #pragma unroll
        for (int j = 0; j < 4; ++j)
            #pragma unroll
            for (int r = 0; r < 4; ++r) acc[i][j][r] = 0.f;

    int4 pah, pal, pbh;
    pah = *(const int4*)(Ah + abase);
    pal = *(const int4*)(Al + abase);
    pbh = *(const int4*)(Bh + bbase);

    for (int kc = 0; kc < 24; ++kc) {
        __syncthreads();                 // prior iter done reading smem
        *(int4*)(smem + OFF_AH + so) = pah;
        *(int4*)(smem + OFF_AL + so) = pal;
        *(int4*)(smem + OFF_BH + so) = pbh;
        __syncthreads();

        if (kc + 1 < 24) {               // prefetch next chunk (overlaps HMMAs)
            size_t ao = abase + (size_t)(kc + 1) * 32;
            size_t bo = bbase + (size_t)(kc + 1) * 32;
            pah = *(const int4*)(Ah + ao);
            pal = *(const int4*)(Al + ao);
            pbh = *(const int4*)(Bh + bo);
        }

        #pragma unroll
        for (int k16 = 0; k16 < 2; ++k16) {
            uint32_t ah[2][4], al[2][4];
            #pragma unroll
            for (int mf = 0; mf < 2; ++mf) {
                int row = wm * 32 + mf * 16 + (lane & 15);
                int c   = 2 * k16 + (lane >> 4);
                uint32_t o = swoff(row, c);
                ldsm_x4(ah[mf][0], ah[mf][1], ah[mf][2], ah[mf][3], sb + OFF_AH + o);
                ldsm_x4(al[mf][0], al[mf][1], al[mf][2], al[mf][3], sb + OFF_AL + o);
            }
            uint32_t bh[4][2];
            #pragma unroll
            for (int np = 0; np < 2; ++np) {
                int g = lane >> 3, l = lane & 7;
                int row = wn * 32 + np * 16 + (g >> 1) * 8 + l;
                int c   = 2 * k16 + (g & 1);
                uint32_t o = swoff(row, c);
                ldsm_x4(bh[np*2][0], bh[np*2][1], bh[np*2+1][0], bh[np*2+1][1],
                        sb + OFF_BH + o);
            }
            #pragma unroll
            for (int mf = 0; mf < 2; ++mf)
                #pragma unroll
                for (int nf = 0; nf < 4; ++nf) {
                    mma16816(acc[mf][nf], ah[mf], bh[nf]);
                    mma16816(acc[mf][nf], al[mf], bh[nf]);
                }
        }
    }

    // ---------------- epilogue ----------------
    const int s = (MODE == 0) ? (tileN * 128) / CH : 0;
    const float scl = (MODE == 0 && s == 0) ? 0.125f : 1.0f;

    #pragma unroll
    for (int mf = 0; mf < 2; ++mf) {
        const int rbase = tileM * 128 + wm * 32 + mf * 16 + (lane >> 2);
        #pragma unroll
        for (int nf = 0; nf < 4; ++nf) {
            const int gcol = tileN * 128 + wn * 32 + nf * 8 + ((lane & 3) << 1);
            const float b0 = bias[gcol], b1 = bias[gcol + 1];
            #pragma unroll
            for (int hh = 0; hh < 2; ++hh) {
                const int row = rbase + hh * 8;
                if (row >= MROWS) continue;
                float v0 = (acc[mf][nf][hh*2+0] + b0) * scl;
                float v1 = (acc[mf][nf][hh*2+1] + b1) * scl;
                if (MODE == 0) {
                    int rem = gcol - s * CH;
                    int hd = rem >> 6, d = rem & 63;
                    int bb = row / SEQ, n = row - bb * SEQ;
                    size_t di = ((size_t)(bb * NH + hd) * SEQ + n) * DH + d;
                    if (s == 0) {
                        uint32_t hp, lp;
                        split2(v0, v1, hp, lp);
                        *(uint32_t*)(g_qh + di) = hp;
                        *(uint32_t*)(g_ql + di) = lp;
                    } else if (s == 1) {
                        *(uint32_t*)(g_kh + di) = pack2h(v0, v1);
                    } else {
                        *(uint32_t*)(g_vh + di) = pack2h(v0, v1);
                    }
                } else {
                    *(float2*)(out + (size_t)row * CH + gcol) = make_float2(v0, v1);
                }
            }
        }
    }
}

// ---------------- mma.sync flash attention (fp16 x2) ------------------------
#define ATT_QH 0
#define ATT_QL 16384
#define ATT_KH 32768
#define ATT_VH 49152
#define ATT_SMEM 65536

__global__ __launch_bounds__(256) void attn_mma()
{
    extern __shared__ char sm[];
    const uint32_t sb = smem_u32(sm);
    const int tid = threadIdx.x, lane = tid & 31, w = tid >> 5;
    const int q0 = blockIdx.x * QT;
    const int hh = blockIdx.y, b = blockIdx.z;
    const size_t hb = (size_t)(b * NH + hh) * SEQ;

    // load Q tile (hi/lo), swizzled
    #pragma unroll
    for (int p = 0; p < 4; ++p) {
        int slot = tid + p * 256;
        int r = slot >> 3, c = slot & 7;
        int gr = q0 + r; if (gr > SEQ - 1) gr = SEQ - 1;
        size_t idx = ((hb + gr) << 6) + c * 8;
        uint32_t so = aswz(r, c);
        *(int4*)(sm + ATT_QH + so) = *(const int4*)(g_qh + idx);
        *(int4*)(sm + ATT_QL + so) = *(const int4*)(g_ql + idx);
    }
    __syncthreads();

    // Q fragments in registers (4 k16 steps over DH)
    uint32_t qh[4][4], ql[4][4];
    #pragma unroll
    for (int kd = 0; kd < 4; ++kd) {
        int row = w * 16 + (lane & 15);
        int c = 2 * kd + (lane >> 4);
        uint32_t o = aswz(row, c);
        ldsm_x4(qh[kd][0], qh[kd][1], qh[kd][2], qh[kd][3], sb + ATT_QH + o);
        ldsm_x4(ql[kd][0], ql[kd][1], ql[kd][2], ql[kd][3], sb + ATT_QL + o);
    }

    float o[8][4];
    #pragma unroll
    for (int i = 0; i < 8; ++i)
        #pragma unroll
        for (int j = 0; j < 4; ++j) o[i][j] = 0.f;
    float m0 = -1e30f, m1 = -1e30f, l0 = 0.f, l1 = 0.f;

    for (int kt = 0; kt < NKT; ++kt) {
        const int k0 = kt * KT;
        __syncthreads();
        #pragma unroll
        for (int p = 0; p < 4; ++p) {
            int slot = tid + p * 256;
            int r = slot >> 3, c = slot & 7;
            int gk = k0 + r; if (gk > SEQ - 1) gk = SEQ - 1;
            size_t idx = ((hb + gk) << 6) + c * 8;
            uint32_t so = aswz(r, c);
            *(int4*)(sm + ATT_KH + so) = *(const int4*)(g_kh + idx);
            *(int4*)(sm + ATT_VH + so) = *(const int4*)(g_vh + idx);
        }
        __syncthreads();

        // ---- S = Q K^T  (2 MMAs per frag: (Qh+Ql)·Kh) ----
        float s[16][4];
        #pragma unroll
        for (int i = 0; i < 16; ++i)
            #pragma unroll
            for (int j = 0; j < 4; ++j) s[i][j] = 0.f;

        #pragma unroll
        for (int kp = 0; kp < 8; ++kp) {
            #pragma unroll
            for (int kd = 0; kd < 4; ++kd) {
                int g = lane >> 3, li = lane & 7;
                int row = kp * 16 + ((g >> 1) << 3) + li;
                int c = 2 * kd + (g & 1);
                uint32_t so = aswz(row, c);
                uint32_t kh4[4];
                ldsm_x4(kh4[0], kh4[1], kh4[2], kh4[3], sb + ATT_KH + so);
                mma2(s[2*kp],   qh[kd], kh4[0], kh4[1]);
                mma2(s[2*kp],   ql[kd], kh4[0], kh4[1]);
                mma2(s[2*kp+1], qh[kd], kh4[2], kh4[3]);
                mma2(s[2*kp+1], ql[kd], kh4[2], kh4[3]);
            }
        }

        // mask invalid keys (last tile)
        if (k0 + KT > SEQ) {
            #pragma unroll
            for (int kn = 0; kn < 16; ++kn) {
                int kg = k0 + kn * 8 + ((lane & 3) << 1);
                if (kg >= SEQ)     { s[kn][0] = -1e30f; s[kn][2] = -1e30f; }
                if (kg + 1 >= SEQ) { s[kn][1] = -1e30f; s[kn][3] = -1e30f; }
            }
        }

        // ---- online softmax ----
        float mx0 = -1e30f, mx1 = -1e30f;
        #pragma unroll
        for (int kn = 0; kn < 16; ++kn) {
            mx0 = fmaxf(mx0, fmaxf(s[kn][0], s[kn][1]));
            mx1 = fmaxf(mx1, fmaxf(s[kn][2], s[kn][3]));
        }
        mx0 = fmaxf(mx0, __shfl_xor_sync(0xffffffffu, mx0, 1));
        mx0 = fmaxf(mx0, __shfl_xor_sync(0xffffffffu, mx0, 2));
        mx1 = fmaxf(mx1, __shfl_xor_sync(0xffffffffu, mx1, 1));
        mx1 = fmaxf(mx1, __shfl_xor_sync(0xffffffffu, mx1, 2));
        float mn0 = fmaxf(m0, mx0), mn1 = fmaxf(m1, mx1);
        float c0 = __expf(m0 - mn0), c1 = __expf(m1 - mn1);
        float sum0 = 0.f, sum1 = 0.f;
        #pragma unroll
        for (int kn = 0; kn < 16; ++kn) {
            s[kn][0] = __expf(s[kn][0] - mn0);
            s[kn][1] = __expf(s[kn][1] - mn0);
            s[kn][2] = __expf(s[kn][2] - mn1);
            s[kn][3] = __expf(s[kn][3] - mn1);
            sum0 += s[kn][0] + s[kn][1];
            sum1 += s[kn][2] + s[kn][3];
        }
        sum0 += __shfl_xor_sync(0xffffffffu, sum0, 1);
        sum0 += __shfl_xor_sync(0xffffffffu, sum0, 2);
        sum1 += __shfl_xor_sync(0xffffffffu, sum1, 1);
        sum1 += __shfl_xor_sync(0xffffffffu, sum1, 2);
        l0 = l0 * c0 + sum0; l1 = l1 * c1 + sum1;
        m0 = mn0; m1 = mn1;
        #pragma unroll
        for (int nf = 0; nf < 8; ++nf) {
            o[nf][0] *= c0; o[nf][1] *= c0;
            o[nf][2] *= c1; o[nf][3] *= c1;
        }

        // ---- PV: O += (Ph+Pl) V  (P split from S regs, V single) ----
        #pragma unroll
        for (int kk = 0; kk < 8; ++kk) {
            uint32_t ph[4], pl[4];
            split2(s[2*kk][0],   s[2*kk][1],   ph[0], pl[0]);
            split2(s[2*kk][2],   s[2*kk][3],   ph[1], pl[1]);
            split2(s[2*kk+1][0], s[2*kk+1][1], ph[2], pl[2]);
            split2(s[2*kk+1][2], s[2*kk+1][3], ph[3], pl[3]);
            #pragma unroll
            for (int d16 = 0; d16 < 4; ++d16) {
                int g = lane >> 3, li = lane & 7;
                int row = kk * 16 + ((g & 1) << 3) + li;
                int c = d16 * 2 + (g >> 1);
                uint32_t so = aswz(row, c);
                uint32_t vh4[4];
                ldsm_x4_t(vh4[0], vh4[1], vh4[2], vh4[3], sb + ATT_VH + so);
                mma2(o[2*d16],   ph, vh4[0], vh4[1]);
                mma2(o[2*d16],   pl, vh4[0], vh4[1]);
                mma2(o[2*d16+1], ph, vh4[2], vh4[3]);
                mma2(o[2*d16+1], pl, vh4[2], vh4[3]);
            }
        }
    }

    // ---- epilogue: o/l -> fp16 hi/lo into proj-A buffers ----
    float r0 = 1.f / l0, r1 = 1.f / l1;
    int rg = lane >> 2, t2 = (lane & 3) << 1;
    int row0 = q0 + w * 16 + rg, row1 = row0 + 8;
    #pragma unroll
    for (int nf = 0; nf < 8; ++nf) {
        int col = hh * DH + nf * 8 + t2;
        if (row0 < SEQ) {
            size_t gi = (size_t)(b * SEQ + row0) * CH + col;
            uint32_t hp, lp;
            split2(o[nf][0] * r0, o[nf][1] * r0, hp, lp);
            *(uint32_t*)(g_xh + gi) = hp;
            *(uint32_t*)(g_xl + gi) = lp;
        }
        if (row1 < SEQ) {
            size_t gi = (size_t)(b * SEQ + row1) * CH + col;
            uint32_t hp, lp;
            split2(o[nf][2] * r1, o[nf][3] * r1, hp, lp);
            *(uint32_t*)(g_xh + gi) = hp;
            *(uint32_t*)(g_xl + gi) = lp;
        }
    }
}

// ---------------------------------------------------------------------------
extern "C" void kernel_launch(void* const* d_in, const int* in_sizes, int n_in,
                              void* d_out, int out_size)
{
    const float* x      = (const float*)d_in[0];
    const float* qkv_w  = (const float*)d_in[1];
    const float* qkv_b  = (const float*)d_in[2];
    const float* proj_w = (const float*)d_in[3];
    const float* proj_b = (const float*)d_in[4];
    float* out = (float*)d_out;

    cudaFuncSetAttribute(attn_mma, cudaFuncAttributeMaxDynamicSharedMemorySize, ATT_SMEM);

    split_kernel<<<(MROWS*CH + 255)/256, 256>>>(x, 0, MROWS*CH);
    split_kernel<<<(QKV_N*CH + 255)/256, 256>>>(qkv_w, 1, QKV_N*CH);
    split_kernel<<<(CH*CH + 255)/256, 256>>>(proj_w, 2, CH*CH);

    mma_gemm<0><<<dim3(QKV_N/128, (MROWS + 127)/128), 512>>>(qkv_b, nullptr);

    attn_mma<<<dim3((SEQ + QT - 1)/QT, NH, BN), 256, ATT_SMEM>>>();

    mma_gemm<1><<<dim3(CH/128, (MROWS + 127)/128), 512>>>(proj_b, out);
}

// round 9
// speedup vs baseline: 2.0326x; 1.1815x over previous
#include <cuda_runtime.h>
#include <cuda_fp16.h>
#include <cstdint>

#define BN   32
#define SEQ  577
#define CH   768
#define NH   12
#define DH   64
#define MROWS (BN*SEQ)      /* 18464 */
#define QKV_N (3*CH)        /* 2304  */
#define QT   128
#define KT   128
#define NKT  5              /* ceil(577/128) */

// ---------------- scratch (__device__ globals; no allocs allowed) ----------
__device__ __half g_qh[BN*NH*SEQ*DH], g_ql[BN*NH*SEQ*DH];   // q hi/lo (scaled)
__device__ __half g_kh[BN*NH*SEQ*DH];                        // k single fp16
__device__ __half g_vh[BN*NH*SEQ*DH];                        // v single fp16
__device__ __half g_xh[MROWS*CH], g_xl[MROWS*CH];            // A hi/lo (x, then attn out)
__device__ __half g_wh[QKV_N*CH];                            // qkv_w single fp16
__device__ __half g_ph[CH*CH];                               // proj_w single fp16

// ---------------- helpers ---------------------------------------------------
__device__ __forceinline__ uint32_t smem_u32(const void* p) {
    uint32_t a;
    asm("{ .reg .u64 t; cvta.to.shared.u64 t, %1; cvt.u32.u64 %0, t; }" : "=r"(a) : "l"(p));
    return a;
}
__device__ __forceinline__ void ldsm_x4(uint32_t& r0, uint32_t& r1,
                                        uint32_t& r2, uint32_t& r3, uint32_t addr) {
    asm volatile("ldmatrix.sync.aligned.m8n8.x4.shared.b16 {%0,%1,%2,%3}, [%4];"
                 : "=r"(r0), "=r"(r1), "=r"(r2), "=r"(r3) : "r"(addr));
}
__device__ __forceinline__ void ldsm_x4_t(uint32_t& r0, uint32_t& r1,
                                          uint32_t& r2, uint32_t& r3, uint32_t addr) {
    asm volatile("ldmatrix.sync.aligned.m8n8.x4.trans.shared.b16 {%0,%1,%2,%3}, [%4];"
                 : "=r"(r0), "=r"(r1), "=r"(r2), "=r"(r3) : "r"(addr));
}
__device__ __forceinline__ void mma16816(float* c, const uint32_t* a, const uint32_t* b) {
    asm volatile("mma.sync.aligned.m16n8k16.row.col.f32.f16.f16.f32 "
                 "{%0,%1,%2,%3}, {%4,%5,%6,%7}, {%8,%9}, {%0,%1,%2,%3};"
                 : "+f"(c[0]), "+f"(c[1]), "+f"(c[2]), "+f"(c[3])
                 : "r"(a[0]), "r"(a[1]), "r"(a[2]), "r"(a[3]), "r"(b[0]), "r"(b[1]));
}
__device__ __forceinline__ void mma2(float* c, const uint32_t* a, uint32_t b0, uint32_t b1) {
    asm volatile("mma.sync.aligned.m16n8k16.row.col.f32.f16.f16.f32 "
                 "{%0,%1,%2,%3}, {%4,%5,%6,%7}, {%8,%9}, {%0,%1,%2,%3};"
                 : "+f"(c[0]), "+f"(c[1]), "+f"(c[2]), "+f"(c[3])
                 : "r"(a[0]), "r"(a[1]), "r"(a[2]), "r"(a[3]), "r"(b0), "r"(b1));
}
// GEMM tile swizzle: 64B rows, 4 chunks
__device__ __forceinline__ uint32_t swoff(int r, int c) {
    return (uint32_t)(r * 64 + ((c ^ ((r >> 1) & 3)) << 4));
}
// attention tile swizzle: 128B rows, 8 chunks
__device__ __forceinline__ uint32_t aswz(int r, int c) {
    return (uint32_t)(r * 128 + ((c ^ (r & 7)) << 4));
}
// fp32 pair -> fp16 hi pair + fp16 lo pair (packed u32)
__device__ __forceinline__ void split2(float x, float y, uint32_t& hi, uint32_t& lo) {
    __half2 h2 = __floats2half2_rn(x, y);
    __half2 l2 = __floats2half2_rn(x - __half2float(__low2half(h2)),
                                   y - __half2float(__high2half(h2)));
    hi = reinterpret_cast<uint32_t&>(h2);
    lo = reinterpret_cast<uint32_t&>(l2);
}
__device__ __forceinline__ uint32_t pack2h(float x, float y) {
    __half2 h2 = __floats2half2_rn(x, y);
    return reinterpret_cast<uint32_t&>(h2);
}

// ---------------- split kernels ---------------------------------------------
// sel 0: x -> g_xh/g_xl (hi/lo).  sel 1: qkv_w -> g_wh.  sel 2: proj_w -> g_ph.
__global__ void split_kernel(const float* __restrict__ src, int sel, int n) {
    int i = blockIdx.x * 256 + threadIdx.x;
    if (i >= n) return;
    float v = src[i];
    __half h = __float2half_rn(v);
    if (sel == 0) {
        g_xh[i] = h;
        g_xl[i] = __float2half_rn(v - __half2float(h));
    } else if (sel == 1) {
        g_wh[i] = h;
    } else {
        g_ph[i] = h;
    }
}

// ---------------- mma.sync fp16x2 GEMM (R3 skeleton) -------------------------
// 128x128 tile, BK=32, 256 thr / 8 warps, warp tile 64x32 (2x4 warp grid),
// single-stage smem + register prefetch. C = (Ah+Al)*Bh.
// MODE 0: A=x(split), B=qkv_w -> q(hi/lo, *0.125), k, v (+bias)
// MODE 1: A=attn-out(split), B=proj_w -> out (+bias)
template<int MODE>
__global__ __launch_bounds__(256) void mma_gemm(const float* __restrict__ bias,
                                                float* __restrict__ out)
{
    __shared__ __align__(16) char smem[24576];
    const uint32_t sb = smem_u32(smem);
    const int tid = threadIdx.x, lane = tid & 31, wid = tid >> 5;
    const int wm = wid & 1, wn = wid >> 1;          // 2 x 4 warp grid, 64x32 tiles
    const int tileN = blockIdx.x, tileM = blockIdx.y;

    const __half* __restrict__ Ah = g_xh;
    const __half* __restrict__ Al = g_xl;
    const __half* __restrict__ Bh = (MODE == 0) ? g_wh : g_ph;

    const uint32_t OFF_AH = 0, OFF_AL = 8192, OFF_BH = 16384;

    // loader: 256 threads, two 16B chunks per buffer (128 rows x 4 chunks)
    const int lr = tid >> 1;            // 0..127
    const int lc = (tid & 1) << 1;      // 0, 2
    int ga = tileM * 128 + lr; if (ga > MROWS - 1) ga = MROWS - 1;
    const int gb = tileN * 128 + lr;
    const size_t abase = (size_t)ga * CH + lc * 8;
    const size_t bbase = (size_t)gb * CH + lc * 8;
    const uint32_t so0 = swoff(lr, lc), so1 = swoff(lr, lc + 1);

    float acc[4][4][4];
    #pragma unroll
    for (int i = 0; i < 4; ++i)
        #pragma unroll
        for (int j = 0; j < 4; ++j)
            #pragma unroll
            for (int r = 0; r < 4; ++r) acc[i][j][r] = 0.f;

    int4 pah[2], pal[2], pbh[2];
    pah[0] = *(const int4*)(Ah + abase); pah[1] = *(const int4*)(Ah + abase + 8);
    pal[0] = *(const int4*)(Al + abase); pal[1] = *(const int4*)(Al + abase + 8);
    pbh[0] = *(const int4*)(Bh + bbase); pbh[1] = *(const int4*)(Bh + bbase + 8);

    for (int kc = 0; kc < 24; ++kc) {
        __syncthreads();                 // prior iter done reading smem
        *(int4*)(smem + OFF_AH + so0) = pah[0]; *(int4*)(smem + OFF_AH + so1) = pah[1];
        *(int4*)(smem + OFF_AL + so0) = pal[0]; *(int4*)(smem + OFF_AL + so1) = pal[1];
        *(int4*)(smem + OFF_BH + so0) = pbh[0]; *(int4*)(smem + OFF_BH + so1) = pbh[1];
        __syncthreads();

        if (kc + 1 < 24) {               // prefetch next chunk (overlaps HMMAs)
            size_t ao = abase + (size_t)(kc + 1) * 32;
            size_t bo = bbase + (size_t)(kc + 1) * 32;
            pah[0] = *(const int4*)(Ah + ao); pah[1] = *(const int4*)(Ah + ao + 8);
            pal[0] = *(const int4*)(Al + ao); pal[1] = *(const int4*)(Al + ao + 8);
            pbh[0] = *(const int4*)(Bh + bo); pbh[1] = *(const int4*)(Bh + bo + 8);
        }

        #pragma unroll
        for (int k16 = 0; k16 < 2; ++k16) {
            uint32_t ah[4][4], al[4][4];
            #pragma unroll
            for (int mf = 0; mf < 4; ++mf) {
                int row = wm * 64 + mf * 16 + (lane & 15);
                int c   = 2 * k16 + (lane >> 4);
                uint32_t o = swoff(row, c);
                ldsm_x4(ah[mf][0], ah[mf][1], ah[mf][2], ah[mf][3], sb + OFF_AH + o);
                ldsm_x4(al[mf][0], al[mf][1], al[mf][2], al[mf][3], sb + OFF_AL + o);
            }
            uint32_t bh[4][2];
            #pragma unroll
            for (int np = 0; np < 2; ++np) {
                int g = lane >> 3, l = lane & 7;
                int row = wn * 32 + np * 16 + (g >> 1) * 8 + l;
                int c   = 2 * k16 + (g & 1);
                uint32_t o = swoff(row, c);
                ldsm_x4(bh[np*2][0], bh[np*2][1], bh[np*2+1][0], bh[np*2+1][1],
                        sb + OFF_BH + o);
            }
            #pragma unroll
            for (int mf = 0; mf < 4; ++mf)
                #pragma unroll
                for (int nf = 0; nf < 4; ++nf) {
                    mma16816(acc[mf][nf], ah[mf], bh[nf]);
                    mma16816(acc[mf][nf], al[mf], bh[nf]);
                }
        }
    }

    // ---------------- epilogue ----------------
    const int s = (MODE == 0) ? (tileN * 128) / CH : 0;
    const float scl = (MODE == 0 && s == 0) ? 0.125f : 1.0f;

    #pragma unroll
    for (int mf = 0; mf < 4; ++mf) {
        const int rbase = tileM * 128 + wm * 64 + mf * 16 + (lane >> 2);
        #pragma unroll
        for (int nf = 0; nf < 4; ++nf) {
            const int gcol = tileN * 128 + wn * 32 + nf * 8 + ((lane & 3) << 1);
            const float b0 = bias[gcol], b1 = bias[gcol + 1];
            #pragma unroll
            for (int hh = 0; hh < 2; ++hh) {
                const int row = rbase + hh * 8;
                if (row >= MROWS) continue;
                float v0 = (acc[mf][nf][hh*2+0] + b0) * scl;
                float v1 = (acc[mf][nf][hh*2+1] + b1) * scl;
                if (MODE == 0) {
                    int rem = gcol - s * CH;
                    int hd = rem >> 6, d = rem & 63;
                    int bb = row / SEQ, n = row - bb * SEQ;
                    size_t di = ((size_t)(bb * NH + hd) * SEQ + n) * DH + d;
                    if (s == 0) {
                        uint32_t hp, lp;
                        split2(v0, v1, hp, lp);
                        *(uint32_t*)(g_qh + di) = hp;
                        *(uint32_t*)(g_ql + di) = lp;
                    } else if (s == 1) {
                        *(uint32_t*)(g_kh + di) = pack2h(v0, v1);
                    } else {
                        *(uint32_t*)(g_vh + di) = pack2h(v0, v1);
                    }
                } else {
                    *(float2*)(out + (size_t)row * CH + gcol) = make_float2(v0, v1);
                }
            }
        }
    }
}

// ---------------- mma.sync flash attention (fp16 x2, unchanged R8) ----------
#define ATT_QH 0
#define ATT_QL 16384
#define ATT_KH 32768
#define ATT_VH 49152
#define ATT_SMEM 65536

__global__ __launch_bounds__(256) void attn_mma()
{
    extern __shared__ char sm[];
    const uint32_t sb = smem_u32(sm);
    const int tid = threadIdx.x, lane = tid & 31, w = tid >> 5;
    const int q0 = blockIdx.x * QT;
    const int hh = blockIdx.y, b = blockIdx.z;
    const size_t hb = (size_t)(b * NH + hh) * SEQ;

    // load Q tile (hi/lo), swizzled
    #pragma unroll
    for (int p = 0; p < 4; ++p) {
        int slot = tid + p * 256;
        int r = slot >> 3, c = slot & 7;
        int gr = q0 + r; if (gr > SEQ - 1) gr = SEQ - 1;
        size_t idx = ((hb + gr) << 6) + c * 8;
        uint32_t so = aswz(r, c);
        *(int4*)(sm + ATT_QH + so) = *(const int4*)(g_qh + idx);
        *(int4*)(sm + ATT_QL + so) = *(const int4*)(g_ql + idx);
    }
    __syncthreads();

    // Q fragments in registers (4 k16 steps over DH)
    uint32_t qh[4][4], ql[4][4];
    #pragma unroll
    for (int kd = 0; kd < 4; ++kd) {
        int row = w * 16 + (lane & 15);
        int c = 2 * kd + (lane >> 4);
        uint32_t o = aswz(row, c);
        ldsm_x4(qh[kd][0], qh[kd][1], qh[kd][2], qh[kd][3], sb + ATT_QH + o);
        ldsm_x4(ql[kd][0], ql[kd][1], ql[kd][2], ql[kd][3], sb + ATT_QL + o);
    }

    float o[8][4];
    #pragma unroll
    for (int i = 0; i < 8; ++i)
        #pragma unroll
        for (int j = 0; j < 4; ++j) o[i][j] = 0.f;
    float m0 = -1e30f, m1 = -1e30f, l0 = 0.f, l1 = 0.f;

    for (int kt = 0; kt < NKT; ++kt) {
        const int k0 = kt * KT;
        __syncthreads();
        #pragma unroll
        for (int p = 0; p < 4; ++p) {
            int slot = tid + p * 256;
            int r = slot >> 3, c = slot & 7;
            int gk = k0 + r; if (gk > SEQ - 1) gk = SEQ - 1;
            size_t idx = ((hb + gk) << 6) + c * 8;
            uint32_t so = aswz(r, c);
            *(int4*)(sm + ATT_KH + so) = *(const int4*)(g_kh + idx);
            *(int4*)(sm + ATT_VH + so) = *(const int4*)(g_vh + idx);
        }
        __syncthreads();

        // ---- S = Q K^T  (2 MMAs per frag: (Qh+Ql)·Kh) ----
        float s[16][4];
        #pragma unroll
        for (int i = 0; i < 16; ++i)
            #pragma unroll
            for (int j = 0; j < 4; ++j) s[i][j] = 0.f;

        #pragma unroll
        for (int kp = 0; kp < 8; ++kp) {
            #pragma unroll
            for (int kd = 0; kd < 4; ++kd) {
                int g = lane >> 3, li = lane & 7;
                int row = kp * 16 + ((g >> 1) << 3) + li;
                int c = 2 * kd + (g & 1);
                uint32_t so = aswz(row, c);
                uint32_t kh4[4];
                ldsm_x4(kh4[0], kh4[1], kh4[2], kh4[3], sb + ATT_KH + so);
                mma2(s[2*kp],   qh[kd], kh4[0], kh4[1]);
                mma2(s[2*kp],   ql[kd], kh4[0], kh4[1]);
                mma2(s[2*kp+1], qh[kd], kh4[2], kh4[3]);
                mma2(s[2*kp+1], ql[kd], kh4[2], kh4[3]);
            }
        }

        // mask invalid keys (last tile)
        if (k0 + KT > SEQ) {
            #pragma unroll
            for (int kn = 0; kn < 16; ++kn) {
                int kg = k0 + kn * 8 + ((lane & 3) << 1);
                if (kg >= SEQ)     { s[kn][0] = -1e30f; s[kn][2] = -1e30f; }
                if (kg + 1 >= SEQ) { s[kn][1] = -1e30f; s[kn][3] = -1e30f; }
            }
        }

        // ---- online softmax ----
        float mx0 = -1e30f, mx1 = -1e30f;
        #pragma unroll
        for (int kn = 0; kn < 16; ++kn) {
            mx0 = fmaxf(mx0, fmaxf(s[kn][0], s[kn][1]));
            mx1 = fmaxf(mx1, fmaxf(s[kn][2], s[kn][3]));
        }
        mx0 = fmaxf(mx0, __shfl_xor_sync(0xffffffffu, mx0, 1));
        mx0 = fmaxf(mx0, __shfl_xor_sync(0xffffffffu, mx0, 2));
        mx1 = fmaxf(mx1, __shfl_xor_sync(0xffffffffu, mx1, 1));
        mx1 = fmaxf(mx1, __shfl_xor_sync(0xffffffffu, mx1, 2));
        float mn0 = fmaxf(m0, mx0), mn1 = fmaxf(m1, mx1);
        float c0 = __expf(m0 - mn0), c1 = __expf(m1 - mn1);
        float sum0 = 0.f, sum1 = 0.f;
        #pragma unroll
        for (int kn = 0; kn < 16; ++kn) {
            s[kn][0] = __expf(s[kn][0] - mn0);
            s[kn][1] = __expf(s[kn][1] - mn0);
            s[kn][2] = __expf(s[kn][2] - mn1);
            s[kn][3] = __expf(s[kn][3] - mn1);
            sum0 += s[kn][0] + s[kn][1];
            sum1 += s[kn][2] + s[kn][3];
        }
        sum0 += __shfl_xor_sync(0xffffffffu, sum0, 1);
        sum0 += __shfl_xor_sync(0xffffffffu, sum0, 2);
        sum1 += __shfl_xor_sync(0xffffffffu, sum1, 1);
        sum1 += __shfl_xor_sync(0xffffffffu, sum1, 2);
        l0 = l0 * c0 + sum0; l1 = l1 * c1 + sum1;
        m0 = mn0; m1 = mn1;
        #pragma unroll
        for (int nf = 0; nf < 8; ++nf) {
            o[nf][0] *= c0; o[nf][1] *= c0;
            o[nf][2] *= c1; o[nf][3] *= c1;
        }

        // ---- PV: O += (Ph+Pl) V  (P split from S regs, V single) ----
        #pragma unroll
        for (int kk = 0; kk < 8; ++kk) {
            uint32_t ph[4], pl[4];
            split2(s[2*kk][0],   s[2*kk][1],   ph[0], pl[0]);
            split2(s[2*kk][2],   s[2*kk][3],   ph[1], pl[1]);
            split2(s[2*kk+1][0], s[2*kk+1][1], ph[2], pl[2]);
            split2(s[2*kk+1][2], s[2*kk+1][3], ph[3], pl[3]);
            #pragma unroll
            for (int d16 = 0; d16 < 4; ++d16) {
                int g = lane >> 3, li = lane & 7;
                int row = kk * 16 + ((g & 1) << 3) + li;
                int c = d16 * 2 + (g >> 1);
                uint32_t so = aswz(row, c);
                uint32_t vh4[4];
                ldsm_x4_t(vh4[0], vh4[1], vh4[2], vh4[3], sb + ATT_VH + so);
                mma2(o[2*d16],   ph, vh4[0], vh4[1]);
                mma2(o[2*d16],   pl, vh4[0], vh4[1]);
                mma2(o[2*d16+1], ph, vh4[2], vh4[3]);
                mma2(o[2*d16+1], pl, vh4[2], vh4[3]);
            }
        }
    }

    // ---- epilogue: o/l -> fp16 hi/lo into proj-A buffers ----
    float r0 = 1.f / l0, r1 = 1.f / l1;
    int rg = lane >> 2, t2 = (lane & 3) << 1;
    int row0 = q0 + w * 16 + rg, row1 = row0 + 8;
    #pragma unroll
    for (int nf = 0; nf < 8; ++nf) {
        int col = hh * DH + nf * 8 + t2;
        if (row0 < SEQ) {
            size_t gi = (size_t)(b * SEQ + row0) * CH + col;
            uint32_t hp, lp;
            split2(o[nf][0] * r0, o[nf][1] * r0, hp, lp);
            *(uint32_t*)(g_xh + gi) = hp;
            *(uint32_t*)(g_xl + gi) = lp;
        }
        if (row1 < SEQ) {
            size_t gi = (size_t)(b * SEQ + row1) * CH + col;
            uint32_t hp, lp;
            split2(o[nf][2] * r1, o[nf][3] * r1, hp, lp);
            *(uint32_t*)(g_xh + gi) = hp;
            *(uint32_t*)(g_xl + gi) = lp;
        }
    }
}

// ---------------------------------------------------------------------------
extern "C" void kernel_launch(void* const* d_in, const int* in_sizes, int n_in,
                              void* d_out, int out_size)
{
    const float* x      = (const float*)d_in[0];
    const float* qkv_w  = (const float*)d_in[1];
    const float* qkv_b  = (const float*)d_in[2];
    const float* proj_w = (const float*)d_in[3];
    const float* proj_b = (const float*)d_in[4];
    float* out = (float*)d_out;

    cudaFuncSetAttribute(attn_mma, cudaFuncAttributeMaxDynamicSharedMemorySize, ATT_SMEM);

    split_kernel<<<(MROWS*CH + 255)/256, 256>>>(x, 0, MROWS*CH);
    split_kernel<<<(QKV_N*CH + 255)/256, 256>>>(qkv_w, 1, QKV_N*CH);
    split_kernel<<<(CH*CH + 255)/256, 256>>>(proj_w, 2, CH*CH);

    mma_gemm<0><<<dim3(QKV_N/128, (MROWS + 127)/128), 256>>>(qkv_b, nullptr);

    attn_mma<<<dim3((SEQ + QT - 1)/QT, NH, BN), 256, ATT_SMEM>>>();

    mma_gemm<1><<<dim3(CH/128, (MROWS + 127)/128), 256>>>(proj_b, out);
}

// round 10
// speedup vs baseline: 2.1799x; 1.0725x over previous
#include <cuda_runtime.h>
#include <cuda_fp16.h>
#include <cstdint>

#define BN   32
#define SEQ  577
#define CH   768
#define NH   12
#define DH   64
#define MROWS (BN*SEQ)      /* 18464 */
#define QKV_N (3*CH)        /* 2304  */
#define QT   128
#define KT   128
#define NKT  5              /* ceil(577/128) */

// ---------------- scratch (__device__ globals; no allocs allowed) ----------
__device__ __half g_qh[BN*NH*SEQ*DH], g_ql[BN*NH*SEQ*DH];   // q hi/lo (scaled)
__device__ __half g_kh[BN*NH*SEQ*DH];                        // k single fp16
__device__ __half g_vh[BN*NH*SEQ*DH];                        // v single fp16
__device__ __half g_xh[MROWS*CH], g_xl[MROWS*CH];            // A hi/lo (x, then attn out)
__device__ __half g_wh[QKV_N*CH];                            // qkv_w single fp16
__device__ __half g_ph[CH*CH];                               // proj_w single fp16

// ---------------- helpers ---------------------------------------------------
__device__ __forceinline__ uint32_t smem_u32(const void* p) {
    uint32_t a;
    asm("{ .reg .u64 t; cvta.to.shared.u64 t, %1; cvt.u32.u64 %0, t; }" : "=r"(a) : "l"(p));
    return a;
}
__device__ __forceinline__ void ldsm_x4(uint32_t& r0, uint32_t& r1,
                                        uint32_t& r2, uint32_t& r3, uint32_t addr) {
    asm volatile("ldmatrix.sync.aligned.m8n8.x4.shared.b16 {%0,%1,%2,%3}, [%4];"
                 : "=r"(r0), "=r"(r1), "=r"(r2), "=r"(r3) : "r"(addr));
}
__device__ __forceinline__ void ldsm_x4_t(uint32_t& r0, uint32_t& r1,
                                          uint32_t& r2, uint32_t& r3, uint32_t addr) {
    asm volatile("ldmatrix.sync.aligned.m8n8.x4.trans.shared.b16 {%0,%1,%2,%3}, [%4];"
                 : "=r"(r0), "=r"(r1), "=r"(r2), "=r"(r3) : "r"(addr));
}
__device__ __forceinline__ void mma16816(float* c, const uint32_t* a, const uint32_t* b) {
    asm volatile("mma.sync.aligned.m16n8k16.row.col.f32.f16.f16.f32 "
                 "{%0,%1,%2,%3}, {%4,%5,%6,%7}, {%8,%9}, {%0,%1,%2,%3};"
                 : "+f"(c[0]), "+f"(c[1]), "+f"(c[2]), "+f"(c[3])
                 : "r"(a[0]), "r"(a[1]), "r"(a[2]), "r"(a[3]), "r"(b[0]), "r"(b[1]));
}
__device__ __forceinline__ void mma2(float* c, const uint32_t* a, uint32_t b0, uint32_t b1) {
    asm volatile("mma.sync.aligned.m16n8k16.row.col.f32.f16.f16.f32 "
                 "{%0,%1,%2,%3}, {%4,%5,%6,%7}, {%8,%9}, {%0,%1,%2,%3};"
                 : "+f"(c[0]), "+f"(c[1]), "+f"(c[2]), "+f"(c[3])
                 : "r"(a[0]), "r"(a[1]), "r"(a[2]), "r"(a[3]), "r"(b0), "r"(b1));
}
// GEMM tile swizzle: 64B rows, 4 chunks
__device__ __forceinline__ uint32_t swoff(int r, int c) {
    return (uint32_t)(r * 64 + ((c ^ ((r >> 1) & 3)) << 4));
}
// attention tile swizzle: 128B rows, 8 chunks
__device__ __forceinline__ uint32_t aswz(int r, int c) {
    return (uint32_t)(r * 128 + ((c ^ (r & 7)) << 4));
}
// fp32 pair -> fp16 hi pair + fp16 lo pair (packed u32)
__device__ __forceinline__ void split2(float x, float y, uint32_t& hi, uint32_t& lo) {
    __half2 h2 = __floats2half2_rn(x, y);
    __half2 l2 = __floats2half2_rn(x - __half2float(__low2half(h2)),
                                   y - __half2float(__high2half(h2)));
    hi = reinterpret_cast<uint32_t&>(h2);
    lo = reinterpret_cast<uint32_t&>(l2);
}
__device__ __forceinline__ uint32_t pack2h(float x, float y) {
    __half2 h2 = __floats2half2_rn(x, y);
    return reinterpret_cast<uint32_t&>(h2);
}

// ---------------- split kernels ---------------------------------------------
__global__ void split_kernel(const float* __restrict__ src, int sel, int n) {
    int i = blockIdx.x * 256 + threadIdx.x;
    if (i >= n) return;
    float v = src[i];
    __half h = __float2half_rn(v);
    if (sel == 0) {
        g_xh[i] = h;
        g_xl[i] = __float2half_rn(v - __half2float(h));
    } else if (sel == 1) {
        g_wh[i] = h;
    } else {
        g_ph[i] = h;
    }
}

// ---------------- mma.sync fp16x2 GEMM, 64x64 warp tiles ---------------------
// CTA 128x128, BK=32, 128 thr / 4 warps (2x2 grid of 64x64 warp tiles),
// single-stage smem, 2 CTAs/SM for cross-CTA latency overlap.
// C = (Ah+Al)*Bh.
// MODE 0: A=x(split), B=qkv_w -> q(hi/lo, *0.125), k, v (+bias)
// MODE 1: A=attn-out(split), B=proj_w -> out (+bias)
template<int MODE>
__global__ __launch_bounds__(128, 2) void mma_gemm(const float* __restrict__ bias,
                                                   float* __restrict__ out)
{
    __shared__ __align__(16) char smem[24576];
    const uint32_t sb = smem_u32(smem);
    const int tid = threadIdx.x, lane = tid & 31, wid = tid >> 5;
    const int wm = wid & 1, wn = wid >> 1;          // 2 x 2 warp grid, 64x64 tiles
    const int tileN = blockIdx.x, tileM = blockIdx.y;

    const __half* __restrict__ Ah = g_xh;
    const __half* __restrict__ Al = g_xl;
    const __half* __restrict__ Bh = (MODE == 0) ? g_wh : g_ph;

    const uint32_t OFF_AH = 0, OFF_AL = 8192, OFF_BH = 16384;

    // loader: 128 rows x 4 chunks(16B) per buffer = 512 slots; 4 per thread
    uint32_t lso[4]; size_t la[4], lb[4];
    #pragma unroll
    for (int i = 0; i < 4; ++i) {
        int slot = tid + (i << 7);
        int r = slot >> 2, c = slot & 3;
        lso[i] = swoff(r, c);
        int ga = tileM * 128 + r; if (ga > MROWS - 1) ga = MROWS - 1;
        la[i] = (size_t)ga * CH + c * 8;
        lb[i] = (size_t)(tileN * 128 + r) * CH + c * 8;
    }

    float acc[4][8][4];
    #pragma unroll
    for (int i = 0; i < 4; ++i)
        #pragma unroll
        for (int j = 0; j < 8; ++j)
            #pragma unroll
            for (int r = 0; r < 4; ++r) acc[i][j][r] = 0.f;

    for (int kc = 0; kc < 24; ++kc) {
        __syncthreads();                 // prior iter done reading smem
        const size_t ko = (size_t)kc * 32;
        #pragma unroll
        for (int i = 0; i < 4; ++i) {
            *(int4*)(smem + OFF_AH + lso[i]) = *(const int4*)(Ah + la[i] + ko);
            *(int4*)(smem + OFF_AL + lso[i]) = *(const int4*)(Al + la[i] + ko);
            *(int4*)(smem + OFF_BH + lso[i]) = *(const int4*)(Bh + lb[i] + ko);
        }
        __syncthreads();

        #pragma unroll
        for (int k16 = 0; k16 < 2; ++k16) {
            uint32_t ah[4][4], al[4][4];
            #pragma unroll
            for (int mf = 0; mf < 4; ++mf) {
                int row = wm * 64 + mf * 16 + (lane & 15);
                int c   = 2 * k16 + (lane >> 4);
                uint32_t o = swoff(row, c);
                ldsm_x4(ah[mf][0], ah[mf][1], ah[mf][2], ah[mf][3], sb + OFF_AH + o);
                ldsm_x4(al[mf][0], al[mf][1], al[mf][2], al[mf][3], sb + OFF_AL + o);
            }
            uint32_t bh[8][2];
            #pragma unroll
            for (int np = 0; np < 4; ++np) {
                int g = lane >> 3, l = lane & 7;
                int row = wn * 64 + np * 16 + (g >> 1) * 8 + l;
                int c   = 2 * k16 + (g & 1);
                uint32_t o = swoff(row, c);
                ldsm_x4(bh[np*2][0], bh[np*2][1], bh[np*2+1][0], bh[np*2+1][1],
                        sb + OFF_BH + o);
            }
            #pragma unroll
            for (int mf = 0; mf < 4; ++mf)
                #pragma unroll
                for (int nf = 0; nf < 8; ++nf) {
                    mma16816(acc[mf][nf], ah[mf], bh[nf]);
                    mma16816(acc[mf][nf], al[mf], bh[nf]);
                }
        }
    }

    // ---------------- epilogue ----------------
    const int s = (MODE == 0) ? (tileN * 128) / CH : 0;
    const float scl = (MODE == 0 && s == 0) ? 0.125f : 1.0f;

    #pragma unroll
    for (int mf = 0; mf < 4; ++mf) {
        const int rbase = tileM * 128 + wm * 64 + mf * 16 + (lane >> 2);
        #pragma unroll
        for (int nf = 0; nf < 8; ++nf) {
            const int gcol = tileN * 128 + wn * 64 + nf * 8 + ((lane & 3) << 1);
            const float b0 = bias[gcol], b1 = bias[gcol + 1];
            #pragma unroll
            for (int hh = 0; hh < 2; ++hh) {
                const int row = rbase + hh * 8;
                if (row >= MROWS) continue;
                float v0 = (acc[mf][nf][hh*2+0] + b0) * scl;
                float v1 = (acc[mf][nf][hh*2+1] + b1) * scl;
                if (MODE == 0) {
                    int rem = gcol - s * CH;
                    int hd = rem >> 6, d = rem & 63;
                    int bb = row / SEQ, n = row - bb * SEQ;
                    size_t di = ((size_t)(bb * NH + hd) * SEQ + n) * DH + d;
                    if (s == 0) {
                        uint32_t hp, lp;
                        split2(v0, v1, hp, lp);
                        *(uint32_t*)(g_qh + di) = hp;
                        *(uint32_t*)(g_ql + di) = lp;
                    } else if (s == 1) {
                        *(uint32_t*)(g_kh + di) = pack2h(v0, v1);
                    } else {
                        *(uint32_t*)(g_vh + di) = pack2h(v0, v1);
                    }
                } else {
                    *(float2*)(out + (size_t)row * CH + gcol) = make_float2(v0, v1);
                }
            }
        }
    }
}

// ---------------- mma.sync flash attention (fp16 x2, unchanged R9) ----------
#define ATT_QH 0
#define ATT_QL 16384
#define ATT_KH 32768
#define ATT_VH 49152
#define ATT_SMEM 65536

__global__ __launch_bounds__(256) void attn_mma()
{
    extern __shared__ char sm[];
    const uint32_t sb = smem_u32(sm);
    const int tid = threadIdx.x, lane = tid & 31, w = tid >> 5;
    const int q0 = blockIdx.x * QT;
    const int hh = blockIdx.y, b = blockIdx.z;
    const size_t hb = (size_t)(b * NH + hh) * SEQ;

    // load Q tile (hi/lo), swizzled
    #pragma unroll
    for (int p = 0; p < 4; ++p) {
        int slot = tid + p * 256;
        int r = slot >> 3, c = slot & 7;
        int gr = q0 + r; if (gr > SEQ - 1) gr = SEQ - 1;
        size_t idx = ((hb + gr) << 6) + c * 8;
        uint32_t so = aswz(r, c);
        *(int4*)(sm + ATT_QH + so) = *(const int4*)(g_qh + idx);
        *(int4*)(sm + ATT_QL + so) = *(const int4*)(g_ql + idx);
    }
    __syncthreads();

    // Q fragments in registers (4 k16 steps over DH)
    uint32_t qh[4][4], ql[4][4];
    #pragma unroll
    for (int kd = 0; kd < 4; ++kd) {
        int row = w * 16 + (lane & 15);
        int c = 2 * kd + (lane >> 4);
        uint32_t o = aswz(row, c);
        ldsm_x4(qh[kd][0], qh[kd][1], qh[kd][2], qh[kd][3], sb + ATT_QH + o);
        ldsm_x4(ql[kd][0], ql[kd][1], ql[kd][2], ql[kd][3], sb + ATT_QL + o);
    }

    float o[8][4];
    #pragma unroll
    for (int i = 0; i < 8; ++i)
        #pragma unroll
        for (int j = 0; j < 4; ++j) o[i][j] = 0.f;
    float m0 = -1e30f, m1 = -1e30f, l0 = 0.f, l1 = 0.f;

    for (int kt = 0; kt < NKT; ++kt) {
        const int k0 = kt * KT;
        __syncthreads();
        #pragma unroll
        for (int p = 0; p < 4; ++p) {
            int slot = tid + p * 256;
            int r = slot >> 3, c = slot & 7;
            int gk = k0 + r; if (gk > SEQ - 1) gk = SEQ - 1;
            size_t idx = ((hb + gk) << 6) + c * 8;
            uint32_t so = aswz(r, c);
            *(int4*)(sm + ATT_KH + so) = *(const int4*)(g_kh + idx);
            *(int4*)(sm + ATT_VH + so) = *(const int4*)(g_vh + idx);
        }
        __syncthreads();

        // ---- S = Q K^T  (2 MMAs per frag: (Qh+Ql)·Kh) ----
        float s[16][4];
        #pragma unroll
        for (int i = 0; i < 16; ++i)
            #pragma unroll
            for (int j = 0; j < 4; ++j) s[i][j] = 0.f;

        #pragma unroll
        for (int kp = 0; kp < 8; ++kp) {
            #pragma unroll
            for (int kd = 0; kd < 4; ++kd) {
                int g = lane >> 3, li = lane & 7;
                int row = kp * 16 + ((g >> 1) << 3) + li;
                int c = 2 * kd + (g & 1);
                uint32_t so = aswz(row, c);
                uint32_t kh4[4];
                ldsm_x4(kh4[0], kh4[1], kh4[2], kh4[3], sb + ATT_KH + so);
                mma2(s[2*kp],   qh[kd], kh4[0], kh4[1]);
                mma2(s[2*kp],   ql[kd], kh4[0], kh4[1]);
                mma2(s[2*kp+1], qh[kd], kh4[2], kh4[3]);
                mma2(s[2*kp+1], ql[kd], kh4[2], kh4[3]);
            }
        }

        // mask invalid keys (last tile)
        if (k0 + KT > SEQ) {
            #pragma unroll
            for (int kn = 0; kn < 16; ++kn) {
                int kg = k0 + kn * 8 + ((lane & 3) << 1);
                if (kg >= SEQ)     { s[kn][0] = -1e30f; s[kn][2] = -1e30f; }
                if (kg + 1 >= SEQ) { s[kn][1] = -1e30f; s[kn][3] = -1e30f; }
            }
        }

        // ---- online softmax ----
        float mx0 = -1e30f, mx1 = -1e30f;
        #pragma unroll
        for (int kn = 0; kn < 16; ++kn) {
            mx0 = fmaxf(mx0, fmaxf(s[kn][0], s[kn][1]));
            mx1 = fmaxf(mx1, fmaxf(s[kn][2], s[kn][3]));
        }
        mx0 = fmaxf(mx0, __shfl_xor_sync(0xffffffffu, mx0, 1));
        mx0 = fmaxf(mx0, __shfl_xor_sync(0xffffffffu, mx0, 2));
        mx1 = fmaxf(mx1, __shfl_xor_sync(0xffffffffu, mx1, 1));
        mx1 = fmaxf(mx1, __shfl_xor_sync(0xffffffffu, mx1, 2));
        float mn0 = fmaxf(m0, mx0), mn1 = fmaxf(m1, mx1);
        float c0 = __expf(m0 - mn0), c1 = __expf(m1 - mn1);
        float sum0 = 0.f, sum1 = 0.f;
        #pragma unroll
        for (int kn = 0; kn < 16; ++kn) {
            s[kn][0] = __expf(s[kn][0] - mn0);
            s[kn][1] = __expf(s[kn][1] - mn0);
            s[kn][2] = __expf(s[kn][2] - mn1);
            s[kn][3] = __expf(s[kn][3] - mn1);
            sum0 += s[kn][0] + s[kn][1];
            sum1 += s[kn][2] + s[kn][3];
        }
        sum0 += __shfl_xor_sync(0xffffffffu, sum0, 1);
        sum0 += __shfl_xor_sync(0xffffffffu, sum0, 2);
        sum1 += __shfl_xor_sync(0xffffffffu, sum1, 1);
        sum1 += __shfl_xor_sync(0xffffffffu, sum1, 2);
        l0 = l0 * c0 + sum0; l1 = l1 * c1 + sum1;
        m0 = mn0; m1 = mn1;
        #pragma unroll
        for (int nf = 0; nf < 8; ++nf) {
            o[nf][0] *= c0; o[nf][1] *= c0;
            o[nf][2] *= c1; o[nf][3] *= c1;
        }

        // ---- PV: O += (Ph+Pl) V  (P split from S regs, V single) ----
        #pragma unroll
        for (int kk = 0; kk < 8; ++kk) {
            uint32_t ph[4], pl[4];
            split2(s[2*kk][0],   s[2*kk][1],   ph[0], pl[0]);
            split2(s[2*kk][2],   s[2*kk][3],   ph[1], pl[1]);
            split2(s[2*kk+1][0], s[2*kk+1][1], ph[2], pl[2]);
            split2(s[2*kk+1][2], s[2*kk+1][3], ph[3], pl[3]);
            #pragma unroll
            for (int d16 = 0; d16 < 4; ++d16) {
                int g = lane >> 3, li = lane & 7;
                int row = kk * 16 + ((g & 1) << 3) + li;
                int c = d16 * 2 + (g >> 1);
                uint32_t so = aswz(row, c);
                uint32_t vh4[4];
                ldsm_x4_t(vh4[0], vh4[1], vh4[2], vh4[3], sb + ATT_VH + so);
                mma2(o[2*d16],   ph, vh4[0], vh4[1]);
                mma2(o[2*d16],   pl, vh4[0], vh4[1]);
                mma2(o[2*d16+1], ph, vh4[2], vh4[3]);
                mma2(o[2*d16+1], pl, vh4[2], vh4[3]);
            }
        }
    }

    // ---- epilogue: o/l -> fp16 hi/lo into proj-A buffers ----
    float r0 = 1.f / l0, r1 = 1.f / l1;
    int rg = lane >> 2, t2 = (lane & 3) << 1;
    int row0 = q0 + w * 16 + rg, row1 = row0 + 8;
    #pragma unroll
    for (int nf = 0; nf < 8; ++nf) {
        int col = hh * DH + nf * 8 + t2;
        if (row0 < SEQ) {
            size_t gi = (size_t)(b * SEQ + row0) * CH + col;
            uint32_t hp, lp;
            split2(o[nf][0] * r0, o[nf][1] * r0, hp, lp);
            *(uint32_t*)(g_xh + gi) = hp;
            *(uint32_t*)(g_xl + gi) = lp;
        }
        if (row1 < SEQ) {
            size_t gi = (size_t)(b * SEQ + row1) * CH + col;
            uint32_t hp, lp;
            split2(o[nf][2] * r1, o[nf][3] * r1, hp, lp);
            *(uint32_t*)(g_xh + gi) = hp;
            *(uint32_t*)(g_xl + gi) = lp;
        }
    }
}

// ---------------------------------------------------------------------------
extern "C" void kernel_launch(void* const* d_in, const int* in_sizes, int n_in,
                              void* d_out, int out_size)
{
    const float* x      = (const float*)d_in[0];
    const float* qkv_w  = (const float*)d_in[1];
    const float* qkv_b  = (const float*)d_in[2];
    const float* proj_w = (const float*)d_in[3];
    const float* proj_b = (const float*)d_in[4];
    float* out = (float*)d_out;

    cudaFuncSetAttribute(attn_mma, cudaFuncAttributeMaxDynamicSharedMemorySize, ATT_SMEM);

    split_kernel<<<(MROWS*CH + 255)/256, 256>>>(x, 0, MROWS*CH);
    split_kernel<<<(QKV_N*CH + 255)/256, 256>>>(qkv_w, 1, QKV_N*CH);
    split_kernel<<<(CH*CH + 255)/256, 256>>>(proj_w, 2, CH*CH);

    mma_gemm<0><<<dim3(QKV_N/128, (MROWS + 127)/128), 128>>>(qkv_b, nullptr);

    attn_mma<<<dim3((SEQ + QT - 1)/QT, NH, BN), 256, ATT_SMEM>>>();

    mma_gemm<1><<<dim3(CH/128, (MROWS + 127)/128), 128>>>(proj_b, out);
}

// round 11
// speedup vs baseline: 2.2893x; 1.0502x over previous
#include <cuda_runtime.h>
#include <cuda_fp16.h>
#include <cstdint>

#define BN   32
#define SEQ  577
#define CH   768
#define NH   12
#define DH   64
#define MROWS (BN*SEQ)      /* 18464 */
#define QKV_N (3*CH)        /* 2304  */
#define QT   128
#define KT   128
#define NKT  5              /* ceil(577/128) */

// ---------------- scratch (__device__ globals; no allocs allowed) ----------
__device__ __half g_qh[BN*NH*SEQ*DH], g_ql[BN*NH*SEQ*DH];   // q hi/lo (scaled)
__device__ __half g_kh[BN*NH*SEQ*DH];                        // k single fp16
__device__ __half g_vh[BN*NH*SEQ*DH];                        // v single fp16
__device__ __half g_xh[MROWS*CH], g_xl[MROWS*CH];            // A hi/lo (x, then attn out)
__device__ __half g_wh[QKV_N*CH];                            // qkv_w single fp16
__device__ __half g_ph[CH*CH];                               // proj_w single fp16

// ---------------- helpers ---------------------------------------------------
__device__ __forceinline__ uint32_t smem_u32(const void* p) {
    uint32_t a;
    asm("{ .reg .u64 t; cvta.to.shared.u64 t, %1; cvt.u32.u64 %0, t; }" : "=r"(a) : "l"(p));
    return a;
}
__device__ __forceinline__ void cpa16(uint32_t dst, const void* src) {
    asm volatile("cp.async.cg.shared.global [%0], [%1], 16;" :: "r"(dst), "l"(src) : "memory");
}
#define CP_COMMIT() asm volatile("cp.async.commit_group;" ::: "memory")
#define CP_WAIT0()  asm volatile("cp.async.wait_group 0;" ::: "memory")

__device__ __forceinline__ void ldsm_x4(uint32_t& r0, uint32_t& r1,
                                        uint32_t& r2, uint32_t& r3, uint32_t addr) {
    asm volatile("ldmatrix.sync.aligned.m8n8.x4.shared.b16 {%0,%1,%2,%3}, [%4];"
                 : "=r"(r0), "=r"(r1), "=r"(r2), "=r"(r3) : "r"(addr));
}
__device__ __forceinline__ void ldsm_x4_t(uint32_t& r0, uint32_t& r1,
                                          uint32_t& r2, uint32_t& r3, uint32_t addr) {
    asm volatile("ldmatrix.sync.aligned.m8n8.x4.trans.shared.b16 {%0,%1,%2,%3}, [%4];"
                 : "=r"(r0), "=r"(r1), "=r"(r2), "=r"(r3) : "r"(addr));
}
__device__ __forceinline__ void mma16816(float* c, const uint32_t* a, const uint32_t* b) {
    asm volatile("mma.sync.aligned.m16n8k16.row.col.f32.f16.f16.f32 "
                 "{%0,%1,%2,%3}, {%4,%5,%6,%7}, {%8,%9}, {%0,%1,%2,%3};"
                 : "+f"(c[0]), "+f"(c[1]), "+f"(c[2]), "+f"(c[3])
                 : "r"(a[0]), "r"(a[1]), "r"(a[2]), "r"(a[3]), "r"(b[0]), "r"(b[1]));
}
__device__ __forceinline__ void mma2(float* c, const uint32_t* a, uint32_t b0, uint32_t b1) {
    asm volatile("mma.sync.aligned.m16n8k16.row.col.f32.f16.f16.f32 "
                 "{%0,%1,%2,%3}, {%4,%5,%6,%7}, {%8,%9}, {%0,%1,%2,%3};"
                 : "+f"(c[0]), "+f"(c[1]), "+f"(c[2]), "+f"(c[3])
                 : "r"(a[0]), "r"(a[1]), "r"(a[2]), "r"(a[3]), "r"(b0), "r"(b1));
}
// GEMM tile swizzle: 64B rows, 4 chunks
__device__ __forceinline__ uint32_t swoff(int r, int c) {
    return (uint32_t)(r * 64 + ((c ^ ((r >> 1) & 3)) << 4));
}
// attention tile swizzle: 128B rows, 8 chunks
__device__ __forceinline__ uint32_t aswz(int r, int c) {
    return (uint32_t)(r * 128 + ((c ^ (r & 7)) << 4));
}
// fp32 pair -> fp16 hi pair + fp16 lo pair (packed u32)
__device__ __forceinline__ void split2(float x, float y, uint32_t& hi, uint32_t& lo) {
    __half2 h2 = __floats2half2_rn(x, y);
    __half2 l2 = __floats2half2_rn(x - __half2float(__low2half(h2)),
                                   y - __half2float(__high2half(h2)));
    hi = reinterpret_cast<uint32_t&>(h2);
    lo = reinterpret_cast<uint32_t&>(l2);
}
__device__ __forceinline__ uint32_t pack2h(float x, float y) {
    __half2 h2 = __floats2half2_rn(x, y);
    return reinterpret_cast<uint32_t&>(h2);
}

// ---------------- split kernels ---------------------------------------------
__global__ void split_kernel(const float* __restrict__ src, int sel, int n) {
    int i = blockIdx.x * 256 + threadIdx.x;
    if (i >= n) return;
    float v = src[i];
    __half h = __float2half_rn(v);
    if (sel == 0) {
        g_xh[i] = h;
        g_xl[i] = __float2half_rn(v - __half2float(h));
    } else if (sel == 1) {
        g_wh[i] = h;
    } else {
        g_ph[i] = h;
    }
}

// ---------------- mma.sync fp16x2 GEMM, 64x64 warp tiles + cp.async ---------
// CTA 128x128, BK=32, 128 thr / 4 warps (2x2 grid of 64x64 warp tiles),
// 2-stage cp.async double buffer, ONE __syncthreads per K-chunk, 2 CTAs/SM.
// C = (Ah+Al)*Bh.
// MODE 0: A=x(split), B=qkv_w -> q(hi/lo, *0.125), k, v (+bias)
// MODE 1: A=attn-out(split), B=proj_w -> out (+bias)
#define G_STG 24576

template<int MODE>
__global__ __launch_bounds__(128, 2) void mma_gemm(const float* __restrict__ bias,
                                                   float* __restrict__ out)
{
    __shared__ __align__(16) char smem[2 * G_STG];
    const uint32_t sb = smem_u32(smem);
    const int tid = threadIdx.x, lane = tid & 31, wid = tid >> 5;
    const int wm = wid & 1, wn = wid >> 1;          // 2 x 2 warp grid, 64x64 tiles
    const int tileN = blockIdx.x, tileM = blockIdx.y;

    const __half* __restrict__ Ah = g_xh;
    const __half* __restrict__ Al = g_xl;
    const __half* __restrict__ Bh = (MODE == 0) ? g_wh : g_ph;

    const uint32_t OFF_AH = 0, OFF_AL = 8192, OFF_BH = 16384;

    // loader: 128 rows x 4 chunks(16B) per buffer = 512 slots; 4 per thread
    uint32_t lso[4]; size_t la[4], lb[4];
    #pragma unroll
    for (int i = 0; i < 4; ++i) {
        int slot = tid + (i << 7);
        int r = slot >> 2, c = slot & 3;
        lso[i] = swoff(r, c);
        int ga = tileM * 128 + r; if (ga > MROWS - 1) ga = MROWS - 1;
        la[i] = (size_t)ga * CH + c * 8;
        lb[i] = (size_t)(tileN * 128 + r) * CH + c * 8;
    }

    float acc[4][8][4];
    #pragma unroll
    for (int i = 0; i < 4; ++i)
        #pragma unroll
        for (int j = 0; j < 8; ++j)
            #pragma unroll
            for (int r = 0; r < 4; ++r) acc[i][j][r] = 0.f;

    // prologue: stage 0 loads (chunk 0)
    {
        const uint32_t st = sb;
        #pragma unroll
        for (int i = 0; i < 4; ++i) {
            cpa16(st + OFF_AH + lso[i], Ah + la[i]);
            cpa16(st + OFF_AL + lso[i], Al + la[i]);
            cpa16(st + OFF_BH + lso[i], Bh + lb[i]);
        }
        CP_COMMIT();
    }

    for (int kc = 0; kc < 24; ++kc) {
        CP_WAIT0();                      // stage kc landed (this thread)
        __syncthreads();                 // CTA-wide: stage kc visible,
                                         // and stage (kc+1)&1 reads (iter kc-1) done
        if (kc + 1 < 24) {               // issue loads for kc+1 into other stage
            const uint32_t st = sb + ((kc + 1) & 1) * G_STG;
            const size_t ko = (size_t)(kc + 1) * 32;
            #pragma unroll
            for (int i = 0; i < 4; ++i) {
                cpa16(st + OFF_AH + lso[i], Ah + la[i] + ko);
                cpa16(st + OFF_AL + lso[i], Al + la[i] + ko);
                cpa16(st + OFF_BH + lso[i], Bh + lb[i] + ko);
            }
            CP_COMMIT();
        }

        const uint32_t st = sb + (kc & 1) * G_STG;
        #pragma unroll
        for (int k16 = 0; k16 < 2; ++k16) {
            uint32_t ah[4][4], al[4][4];
            #pragma unroll
            for (int mf = 0; mf < 4; ++mf) {
                int row = wm * 64 + mf * 16 + (lane & 15);
                int c   = 2 * k16 + (lane >> 4);
                uint32_t o = swoff(row, c);
                ldsm_x4(ah[mf][0], ah[mf][1], ah[mf][2], ah[mf][3], st + OFF_AH + o);
                ldsm_x4(al[mf][0], al[mf][1], al[mf][2], al[mf][3], st + OFF_AL + o);
            }
            uint32_t bh[8][2];
            #pragma unroll
            for (int np = 0; np < 4; ++np) {
                int g = lane >> 3, l = lane & 7;
                int row = wn * 64 + np * 16 + (g >> 1) * 8 + l;
                int c   = 2 * k16 + (g & 1);
                uint32_t o = swoff(row, c);
                ldsm_x4(bh[np*2][0], bh[np*2][1], bh[np*2+1][0], bh[np*2+1][1],
                        st + OFF_BH + o);
            }
            #pragma unroll
            for (int mf = 0; mf < 4; ++mf)
                #pragma unroll
                for (int nf = 0; nf < 8; ++nf) {
                    mma16816(acc[mf][nf], ah[mf], bh[nf]);
                    mma16816(acc[mf][nf], al[mf], bh[nf]);
                }
        }
    }

    // ---------------- epilogue ----------------
    const int s = (MODE == 0) ? (tileN * 128) / CH : 0;
    const float scl = (MODE == 0 && s == 0) ? 0.125f : 1.0f;

    #pragma unroll
    for (int mf = 0; mf < 4; ++mf) {
        const int rbase = tileM * 128 + wm * 64 + mf * 16 + (lane >> 2);
        #pragma unroll
        for (int nf = 0; nf < 8; ++nf) {
            const int gcol = tileN * 128 + wn * 64 + nf * 8 + ((lane & 3) << 1);
            const float b0 = bias[gcol], b1 = bias[gcol + 1];
            #pragma unroll
            for (int hh = 0; hh < 2; ++hh) {
                const int row = rbase + hh * 8;
                if (row >= MROWS) continue;
                float v0 = (acc[mf][nf][hh*2+0] + b0) * scl;
                float v1 = (acc[mf][nf][hh*2+1] + b1) * scl;
                if (MODE == 0) {
                    int rem = gcol - s * CH;
                    int hd = rem >> 6, d = rem & 63;
                    int bb = row / SEQ, n = row - bb * SEQ;
                    size_t di = ((size_t)(bb * NH + hd) * SEQ + n) * DH + d;
                    if (s == 0) {
                        uint32_t hp, lp;
                        split2(v0, v1, hp, lp);
                        *(uint32_t*)(g_qh + di) = hp;
                        *(uint32_t*)(g_ql + di) = lp;
                    } else if (s == 1) {
                        *(uint32_t*)(g_kh + di) = pack2h(v0, v1);
                    } else {
                        *(uint32_t*)(g_vh + di) = pack2h(v0, v1);
                    }
                } else {
                    *(float2*)(out + (size_t)row * CH + gcol) = make_float2(v0, v1);
                }
            }
        }
    }
}

// ---------------- mma.sync flash attention (fp16 x2, unchanged R10) ---------
#define ATT_QH 0
#define ATT_QL 16384
#define ATT_KH 32768
#define ATT_VH 49152
#define ATT_SMEM 65536

__global__ __launch_bounds__(256) void attn_mma()
{
    extern __shared__ char sm[];
    const uint32_t sb = smem_u32(sm);
    const int tid = threadIdx.x, lane = tid & 31, w = tid >> 5;
    const int q0 = blockIdx.x * QT;
    const int hh = blockIdx.y, b = blockIdx.z;
    const size_t hb = (size_t)(b * NH + hh) * SEQ;

    // load Q tile (hi/lo), swizzled
    #pragma unroll
    for (int p = 0; p < 4; ++p) {
        int slot = tid + p * 256;
        int r = slot >> 3, c = slot & 7;
        int gr = q0 + r; if (gr > SEQ - 1) gr = SEQ - 1;
        size_t idx = ((hb + gr) << 6) + c * 8;
        uint32_t so = aswz(r, c);
        *(int4*)(sm + ATT_QH + so) = *(const int4*)(g_qh + idx);
        *(int4*)(sm + ATT_QL + so) = *(const int4*)(g_ql + idx);
    }
    __syncthreads();

    // Q fragments in registers (4 k16 steps over DH)
    uint32_t qh[4][4], ql[4][4];
    #pragma unroll
    for (int kd = 0; kd < 4; ++kd) {
        int row = w * 16 + (lane & 15);
        int c = 2 * kd + (lane >> 4);
        uint32_t o = aswz(row, c);
        ldsm_x4(qh[kd][0], qh[kd][1], qh[kd][2], qh[kd][3], sb + ATT_QH + o);
        ldsm_x4(ql[kd][0], ql[kd][1], ql[kd][2], ql[kd][3], sb + ATT_QL + o);
    }

    float o[8][4];
    #pragma unroll
    for (int i = 0; i < 8; ++i)
        #pragma unroll
        for (int j = 0; j < 4; ++j) o[i][j] = 0.f;
    float m0 = -1e30f, m1 = -1e30f, l0 = 0.f, l1 = 0.f;

    for (int kt = 0; kt < NKT; ++kt) {
        const int k0 = kt * KT;
        __syncthreads();
        #pragma unroll
        for (int p = 0; p < 4; ++p) {
            int slot = tid + p * 256;
            int r = slot >> 3, c = slot & 7;
            int gk = k0 + r; if (gk > SEQ - 1) gk = SEQ - 1;
            size_t idx = ((hb + gk) << 6) + c * 8;
            uint32_t so = aswz(r, c);
            *(int4*)(sm + ATT_KH + so) = *(const int4*)(g_kh + idx);
            *(int4*)(sm + ATT_VH + so) = *(const int4*)(g_vh + idx);
        }
        __syncthreads();

        // ---- S = Q K^T  (2 MMAs per frag: (Qh+Ql)·Kh) ----
        float s[16][4];
        #pragma unroll
        for (int i = 0; i < 16; ++i)
            #pragma unroll
            for (int j = 0; j < 4; ++j) s[i][j] = 0.f;

        #pragma unroll
        for (int kp = 0; kp < 8; ++kp) {
            #pragma unroll
            for (int kd = 0; kd < 4; ++kd) {
                int g = lane >> 3, li = lane & 7;
                int row = kp * 16 + ((g >> 1) << 3) + li;
                int c = 2 * kd + (g & 1);
                uint32_t so = aswz(row, c);
                uint32_t kh4[4];
                ldsm_x4(kh4[0], kh4[1], kh4[2], kh4[3], sb + ATT_KH + so);
                mma2(s[2*kp],   qh[kd], kh4[0], kh4[1]);
                mma2(s[2*kp],   ql[kd], kh4[0], kh4[1]);
                mma2(s[2*kp+1], qh[kd], kh4[2], kh4[3]);
                mma2(s[2*kp+1], ql[kd], kh4[2], kh4[3]);
            }
        }

        // mask invalid keys (last tile)
        if (k0 + KT > SEQ) {
            #pragma unroll
            for (int kn = 0; kn < 16; ++kn) {
                int kg = k0 + kn * 8 + ((lane & 3) << 1);
                if (kg >= SEQ)     { s[kn][0] = -1e30f; s[kn][2] = -1e30f; }
                if (kg + 1 >= SEQ) { s[kn][1] = -1e30f; s[kn][3] = -1e30f; }
            }
        }

        // ---- online softmax ----
        float mx0 = -1e30f, mx1 = -1e30f;
        #pragma unroll
        for (int kn = 0; kn < 16; ++kn) {
            mx0 = fmaxf(mx0, fmaxf(s[kn][0], s[kn][1]));
            mx1 = fmaxf(mx1, fmaxf(s[kn][2], s[kn][3]));
        }
        mx0 = fmaxf(mx0, __shfl_xor_sync(0xffffffffu, mx0, 1));
        mx0 = fmaxf(mx0, __shfl_xor_sync(0xffffffffu, mx0, 2));
        mx1 = fmaxf(mx1, __shfl_xor_sync(0xffffffffu, mx1, 1));
        mx1 = fmaxf(mx1, __shfl_xor_sync(0xffffffffu, mx1, 2));
        float mn0 = fmaxf(m0, mx0), mn1 = fmaxf(m1, mx1);
        float c0 = __expf(m0 - mn0), c1 = __expf(m1 - mn1);
        float sum0 = 0.f, sum1 = 0.f;
        #pragma unroll
        for (int kn = 0; kn < 16; ++kn) {
            s[kn][0] = __expf(s[kn][0] - mn0);
            s[kn][1] = __expf(s[kn][1] - mn0);
            s[kn][2] = __expf(s[kn][2] - mn1);
            s[kn][3] = __expf(s[kn][3] - mn1);
            sum0 += s[kn][0] + s[kn][1];
            sum1 += s[kn][2] + s[kn][3];
        }
        sum0 += __shfl_xor_sync(0xffffffffu, sum0, 1);
        sum0 += __shfl_xor_sync(0xffffffffu, sum0, 2);
        sum1 += __shfl_xor_sync(0xffffffffu, sum1, 1);
        sum1 += __shfl_xor_sync(0xffffffffu, sum1, 2);
        l0 = l0 * c0 + sum0; l1 = l1 * c1 + sum1;
        m0 = mn0; m1 = mn1;
        #pragma unroll
        for (int nf = 0; nf < 8; ++nf) {
            o[nf][0] *= c0; o[nf][1] *= c0;
            o[nf][2] *= c1; o[nf][3] *= c1;
        }

        // ---- PV: O += (Ph+Pl) V  (P split from S regs, V single) ----
        #pragma unroll
        for (int kk = 0; kk < 8; ++kk) {
            uint32_t ph[4], pl[4];
            split2(s[2*kk][0],   s[2*kk][1],   ph[0], pl[0]);
            split2(s[2*kk][2],   s[2*kk][3],   ph[1], pl[1]);
            split2(s[2*kk+1][0], s[2*kk+1][1], ph[2], pl[2]);
            split2(s[2*kk+1][2], s[2*kk+1][3], ph[3], pl[3]);
            #pragma unroll
            for (int d16 = 0; d16 < 4; ++d16) {
                int g = lane >> 3, li = lane & 7;
                int row = kk * 16 + ((g & 1) << 3) + li;
                int c = d16 * 2 + (g >> 1);
                uint32_t so = aswz(row, c);
                uint32_t vh4[4];
                ldsm_x4_t(vh4[0], vh4[1], vh4[2], vh4[3], sb + ATT_VH + so);
                mma2(o[2*d16],   ph, vh4[0], vh4[1]);
                mma2(o[2*d16],   pl, vh4[0], vh4[1]);
                mma2(o[2*d16+1], ph, vh4[2], vh4[3]);
                mma2(o[2*d16+1], pl, vh4[2], vh4[3]);
            }
        }
    }

    // ---- epilogue: o/l -> fp16 hi/lo into proj-A buffers ----
    float r0 = 1.f / l0, r1 = 1.f / l1;
    int rg = lane >> 2, t2 = (lane & 3) << 1;
    int row0 = q0 + w * 16 + rg, row1 = row0 + 8;
    #pragma unroll
    for (int nf = 0; nf < 8; ++nf) {
        int col = hh * DH + nf * 8 + t2;
        if (row0 < SEQ) {
            size_t gi = (size_t)(b * SEQ + row0) * CH + col;
            uint32_t hp, lp;
            split2(o[nf][0] * r0, o[nf][1] * r0, hp, lp);
            *(uint32_t*)(g_xh + gi) = hp;
            *(uint32_t*)(g_xl + gi) = lp;
        }
        if (row1 < SEQ) {
            size_t gi = (size_t)(b * SEQ + row1) * CH + col;
            uint32_t hp, lp;
            split2(o[nf][2] * r1, o[nf][3] * r1, hp, lp);
            *(uint32_t*)(g_xh + gi) = hp;
            *(uint32_t*)(g_xl + gi) = lp;
        }
    }
}

// ---------------------------------------------------------------------------
extern "C" void kernel_launch(void* const* d_in, const int* in_sizes, int n_in,
                              void* d_out, int out_size)
{
    const float* x      = (const float*)d_in[0];
    const float* qkv_w  = (const float*)d_in[1];
    const float* qkv_b  = (const float*)d_in[2];
    const float* proj_w = (const float*)d_in[3];
    const float* proj_b = (const float*)d_in[4];
    float* out = (float*)d_out;

    cudaFuncSetAttribute(attn_mma, cudaFuncAttributeMaxDynamicSharedMemorySize, ATT_SMEM);

    split_kernel<<<(MROWS*CH + 255)/256, 256>>>(x, 0, MROWS*CH);
    split_kernel<<<(QKV_N*CH + 255)/256, 256>>>(qkv_w, 1, QKV_N*CH);
    split_kernel<<<(CH*CH + 255)/256, 256>>>(proj_w, 2, CH*CH);

    mma_gemm<0><<<dim3(QKV_N/128, (MROWS + 127)/128), 128>>>(qkv_b, nullptr);

    attn_mma<<<dim3((SEQ + QT - 1)/QT, NH, BN), 256, ATT_SMEM>>>();

    mma_gemm<1><<<dim3(CH/128, (MROWS + 127)/128), 128>>>(proj_b, out);
}

// round 12
// speedup vs baseline: 2.4327x; 1.0627x over previous
#include <cuda_runtime.h>
#include <cuda_fp16.h>
#include <cstdint>

#define BN   32
#define SEQ  577
#define CH   768
#define NH   12
#define DH   64
#define MROWS (BN*SEQ)      /* 18464 */
#define QKV_N (3*CH)        /* 2304  */
#define QT   128
#define KT   128
#define NKT  5              /* ceil(577/128) */

// ---------------- scratch (__device__ globals; no allocs allowed) ----------
__device__ __half g_qh[BN*NH*SEQ*DH], g_ql[BN*NH*SEQ*DH];   // q hi/lo (scaled)
__device__ __half g_kh[BN*NH*SEQ*DH];                        // k single fp16
__device__ __half g_vh[BN*NH*SEQ*DH];                        // v single fp16
__device__ __half g_xh[MROWS*CH], g_xl[MROWS*CH];            // A hi/lo (x, then attn out)
__device__ __half g_wh[QKV_N*CH];                            // qkv_w single fp16
__device__ __half g_ph[CH*CH];                               // proj_w single fp16

// ---------------- helpers ---------------------------------------------------
__device__ __forceinline__ uint32_t smem_u32(const void* p) {
    uint32_t a;
    asm("{ .reg .u64 t; cvta.to.shared.u64 t, %1; cvt.u32.u64 %0, t; }" : "=r"(a) : "l"(p));
    return a;
}
__device__ __forceinline__ void cpa16(uint32_t dst, const void* src) {
    asm volatile("cp.async.cg.shared.global [%0], [%1], 16;" :: "r"(dst), "l"(src) : "memory");
}
#define CP_COMMIT() asm volatile("cp.async.commit_group;" ::: "memory")
#define CP_WAIT0()  asm volatile("cp.async.wait_group 0;" ::: "memory")

__device__ __forceinline__ void ldsm_x4(uint32_t& r0, uint32_t& r1,
                                        uint32_t& r2, uint32_t& r3, uint32_t addr) {
    asm volatile("ldmatrix.sync.aligned.m8n8.x4.shared.b16 {%0,%1,%2,%3}, [%4];"
                 : "=r"(r0), "=r"(r1), "=r"(r2), "=r"(r3) : "r"(addr));
}
__device__ __forceinline__ void ldsm_x4_t(uint32_t& r0, uint32_t& r1,
                                          uint32_t& r2, uint32_t& r3, uint32_t addr) {
    asm volatile("ldmatrix.sync.aligned.m8n8.x4.trans.shared.b16 {%0,%1,%2,%3}, [%4];"
                 : "=r"(r0), "=r"(r1), "=r"(r2), "=r"(r3) : "r"(addr));
}
__device__ __forceinline__ void mma16816(float* c, const uint32_t* a, const uint32_t* b) {
    asm volatile("mma.sync.aligned.m16n8k16.row.col.f32.f16.f16.f32 "
                 "{%0,%1,%2,%3}, {%4,%5,%6,%7}, {%8,%9}, {%0,%1,%2,%3};"
                 : "+f"(c[0]), "+f"(c[1]), "+f"(c[2]), "+f"(c[3])
                 : "r"(a[0]), "r"(a[1]), "r"(a[2]), "r"(a[3]), "r"(b[0]), "r"(b[1]));
}
__device__ __forceinline__ void mma2(float* c, const uint32_t* a, uint32_t b0, uint32_t b1) {
    asm volatile("mma.sync.aligned.m16n8k16.row.col.f32.f16.f16.f32 "
                 "{%0,%1,%2,%3}, {%4,%5,%6,%7}, {%8,%9}, {%0,%1,%2,%3};"
                 : "+f"(c[0]), "+f"(c[1]), "+f"(c[2]), "+f"(c[3])
                 : "r"(a[0]), "r"(a[1]), "r"(a[2]), "r"(a[3]), "r"(b0), "r"(b1));
}
// GEMM tile swizzle: 64B rows, 4 chunks
__device__ __forceinline__ uint32_t swoff(int r, int c) {
    return (uint32_t)(r * 64 + ((c ^ ((r >> 1) & 3)) << 4));
}
// attention tile swizzle: 128B rows, 8 chunks
__device__ __forceinline__ uint32_t aswz(int r, int c) {
    return (uint32_t)(r * 128 + ((c ^ (r & 7)) << 4));
}
// fp32 pair -> fp16 hi pair + fp16 lo pair (packed u32)
__device__ __forceinline__ void split2(float x, float y, uint32_t& hi, uint32_t& lo) {
    __half2 h2 = __floats2half2_rn(x, y);
    __half2 l2 = __floats2half2_rn(x - __half2float(__low2half(h2)),
                                   y - __half2float(__high2half(h2)));
    hi = reinterpret_cast<uint32_t&>(h2);
    lo = reinterpret_cast<uint32_t&>(l2);
}
__device__ __forceinline__ uint32_t pack2h(float x, float y) {
    __half2 h2 = __floats2half2_rn(x, y);
    return reinterpret_cast<uint32_t&>(h2);
}

// ---------------- split kernels ---------------------------------------------
__global__ void split_kernel(const float* __restrict__ src, int sel, int n) {
    int i = blockIdx.x * 256 + threadIdx.x;
    if (i >= n) return;
    float v = src[i];
    __half h = __float2half_rn(v);
    if (sel == 0) {
        g_xh[i] = h;
        g_xl[i] = __float2half_rn(v - __half2float(h));
    } else if (sel == 1) {
        g_wh[i] = h;
    } else {
        g_ph[i] = h;
    }
}

// ---------------- mma.sync fp16x2 GEMM, 64x64 warp tiles + cp.async ---------
// (unchanged from R11: CTA 128x128, BK=32, 4 warps, 2-stage cp.async, 2 CTA/SM)
#define G_STG 24576

template<int MODE>
__global__ __launch_bounds__(128, 2) void mma_gemm(const float* __restrict__ bias,
                                                   float* __restrict__ out)
{
    __shared__ __align__(16) char smem[2 * G_STG];
    const uint32_t sb = smem_u32(smem);
    const int tid = threadIdx.x, lane = tid & 31, wid = tid >> 5;
    const int wm = wid & 1, wn = wid >> 1;          // 2 x 2 warp grid, 64x64 tiles
    const int tileN = blockIdx.x, tileM = blockIdx.y;

    const __half* __restrict__ Ah = g_xh;
    const __half* __restrict__ Al = g_xl;
    const __half* __restrict__ Bh = (MODE == 0) ? g_wh : g_ph;

    const uint32_t OFF_AH = 0, OFF_AL = 8192, OFF_BH = 16384;

    uint32_t lso[4]; size_t la[4], lb[4];
    #pragma unroll
    for (int i = 0; i < 4; ++i) {
        int slot = tid + (i << 7);
        int r = slot >> 2, c = slot & 3;
        lso[i] = swoff(r, c);
        int ga = tileM * 128 + r; if (ga > MROWS - 1) ga = MROWS - 1;
        la[i] = (size_t)ga * CH + c * 8;
        lb[i] = (size_t)(tileN * 128 + r) * CH + c * 8;
    }

    float acc[4][8][4];
    #pragma unroll
    for (int i = 0; i < 4; ++i)
        #pragma unroll
        for (int j = 0; j < 8; ++j)
            #pragma unroll
            for (int r = 0; r < 4; ++r) acc[i][j][r] = 0.f;

    {
        const uint32_t st = sb;
        #pragma unroll
        for (int i = 0; i < 4; ++i) {
            cpa16(st + OFF_AH + lso[i], Ah + la[i]);
            cpa16(st + OFF_AL + lso[i], Al + la[i]);
            cpa16(st + OFF_BH + lso[i], Bh + lb[i]);
        }
        CP_COMMIT();
    }

    for (int kc = 0; kc < 24; ++kc) {
        CP_WAIT0();
        __syncthreads();
        if (kc + 1 < 24) {
            const uint32_t st = sb + ((kc + 1) & 1) * G_STG;
            const size_t ko = (size_t)(kc + 1) * 32;
            #pragma unroll
            for (int i = 0; i < 4; ++i) {
                cpa16(st + OFF_AH + lso[i], Ah + la[i] + ko);
                cpa16(st + OFF_AL + lso[i], Al + la[i] + ko);
                cpa16(st + OFF_BH + lso[i], Bh + lb[i] + ko);
            }
            CP_COMMIT();
        }

        const uint32_t st = sb + (kc & 1) * G_STG;
        #pragma unroll
        for (int k16 = 0; k16 < 2; ++k16) {
            uint32_t ah[4][4], al[4][4];
            #pragma unroll
            for (int mf = 0; mf < 4; ++mf) {
                int row = wm * 64 + mf * 16 + (lane & 15);
                int c   = 2 * k16 + (lane >> 4);
                uint32_t o = swoff(row, c);
                ldsm_x4(ah[mf][0], ah[mf][1], ah[mf][2], ah[mf][3], st + OFF_AH + o);
                ldsm_x4(al[mf][0], al[mf][1], al[mf][2], al[mf][3], st + OFF_AL + o);
            }
            uint32_t bh[8][2];
            #pragma unroll
            for (int np = 0; np < 4; ++np) {
                int g = lane >> 3, l = lane & 7;
                int row = wn * 64 + np * 16 + (g >> 1) * 8 + l;
                int c   = 2 * k16 + (g & 1);
                uint32_t o = swoff(row, c);
                ldsm_x4(bh[np*2][0], bh[np*2][1], bh[np*2+1][0], bh[np*2+1][1],
                        st + OFF_BH + o);
            }
            #pragma unroll
            for (int mf = 0; mf < 4; ++mf)
                #pragma unroll
                for (int nf = 0; nf < 8; ++nf) {
                    mma16816(acc[mf][nf], ah[mf], bh[nf]);
                    mma16816(acc[mf][nf], al[mf], bh[nf]);
                }
        }
    }

    const int s = (MODE == 0) ? (tileN * 128) / CH : 0;
    const float scl = (MODE == 0 && s == 0) ? 0.125f : 1.0f;

    #pragma unroll
    for (int mf = 0; mf < 4; ++mf) {
        const int rbase = tileM * 128 + wm * 64 + mf * 16 + (lane >> 2);
        #pragma unroll
        for (int nf = 0; nf < 8; ++nf) {
            const int gcol = tileN * 128 + wn * 64 + nf * 8 + ((lane & 3) << 1);
            const float b0 = bias[gcol], b1 = bias[gcol + 1];
            #pragma unroll
            for (int hh = 0; hh < 2; ++hh) {
                const int row = rbase + hh * 8;
                if (row >= MROWS) continue;
                float v0 = (acc[mf][nf][hh*2+0] + b0) * scl;
                float v1 = (acc[mf][nf][hh*2+1] + b1) * scl;
                if (MODE == 0) {
                    int rem = gcol - s * CH;
                    int hd = rem >> 6, d = rem & 63;
                    int bb = row / SEQ, n = row - bb * SEQ;
                    size_t di = ((size_t)(bb * NH + hd) * SEQ + n) * DH + d;
                    if (s == 0) {
                        uint32_t hp, lp;
                        split2(v0, v1, hp, lp);
                        *(uint32_t*)(g_qh + di) = hp;
                        *(uint32_t*)(g_ql + di) = lp;
                    } else if (s == 1) {
                        *(uint32_t*)(g_kh + di) = pack2h(v0, v1);
                    } else {
                        *(uint32_t*)(g_vh + di) = pack2h(v0, v1);
                    }
                } else {
                    *(float2*)(out + (size_t)row * CH + gcol) = make_float2(v0, v1);
                }
            }
        }
    }
}

// ---------------- mma.sync flash attention, 2-stage cp.async K/V ------------
// smem 64KB: [0:16K) QH / stage1-KH, [16K:32K) QL / stage1-VH,
//            [32K:48K) stage0-KH, [48K:64K) stage0-VH.
// Q region is reused as stage 1 after Q fragments are hoisted to registers.
#define ATT_SMEM 65536

__global__ __launch_bounds__(256) void attn_mma()
{
    extern __shared__ char sm[];
    const uint32_t sb = smem_u32(sm);
    const int tid = threadIdx.x, lane = tid & 31, w = tid >> 5;
    const int q0 = blockIdx.x * QT;
    const int hh = blockIdx.y, b = blockIdx.z;
    const size_t hb = (size_t)(b * NH + hh) * SEQ;

    // per-thread loader slots (128 rows x 8 chunks = 1024 slots, 4 per thread)
    int lr4[4]; uint32_t lso[4];
    #pragma unroll
    for (int p = 0; p < 4; ++p) {
        int slot = tid + (p << 8);
        lr4[p] = slot >> 3;
        lso[p] = aswz(slot >> 3, slot & 7) + ((slot & 7) << 0) * 0; // aswz already has chunk
    }
    // column byte offset within row for each slot
    int lc4[4];
    #pragma unroll
    for (int p = 0; p < 4; ++p) { int slot = tid + (p << 8); lc4[p] = (slot & 7) * 8; }

    // prologue: Q (hi/lo) + KV tile 0 via cp.async, one group
    #pragma unroll
    for (int p = 0; p < 4; ++p) {
        int gr = q0 + lr4[p]; if (gr > SEQ - 1) gr = SEQ - 1;
        size_t qi = ((hb + gr) << 6) + lc4[p];
        cpa16(sb + 0     + lso[p], g_qh + qi);
        cpa16(sb + 16384 + lso[p], g_ql + qi);
        int gk = lr4[p]; if (gk > SEQ - 1) gk = SEQ - 1;
        size_t ki = ((hb + gk) << 6) + lc4[p];
        cpa16(sb + 32768 + lso[p], g_kh + ki);
        cpa16(sb + 49152 + lso[p], g_vh + ki);
    }
    CP_COMMIT();
    CP_WAIT0();
    __syncthreads();

    // Q fragments -> registers (Q smem region is dead afterwards)
    uint32_t qh[4][4], ql[4][4];
    #pragma unroll
    for (int kd = 0; kd < 4; ++kd) {
        int row = w * 16 + (lane & 15);
        int c = 2 * kd + (lane >> 4);
        uint32_t o = aswz(row, c);
        ldsm_x4(qh[kd][0], qh[kd][1], qh[kd][2], qh[kd][3], sb + 0 + o);
        ldsm_x4(ql[kd][0], ql[kd][1], ql[kd][2], ql[kd][3], sb + 16384 + o);
    }
    __syncthreads();   // all warps done reading Q before stage1 overwrites it

    float o[8][4];
    #pragma unroll
    for (int i = 0; i < 8; ++i)
        #pragma unroll
        for (int j = 0; j < 4; ++j) o[i][j] = 0.f;
    float m0 = -1e30f, m1 = -1e30f, l0 = 0.f, l1 = 0.f;

    for (int kt = 0; kt < NKT; ++kt) {
        // issue next tile into the other stage (stage kt&1==0 -> 32768, ==1 -> 0)
        if (kt + 1 < NKT) {
            const uint32_t st = sb + (((kt + 1) & 1) ? 0u : 32768u);
            const int k0n = (kt + 1) * KT;
            #pragma unroll
            for (int p = 0; p < 4; ++p) {
                int gk = k0n + lr4[p]; if (gk > SEQ - 1) gk = SEQ - 1;
                size_t ki = ((hb + gk) << 6) + lc4[p];
                cpa16(st + 0     + lso[p], g_kh + ki);
                cpa16(st + 16384 + lso[p], g_vh + ki);
            }
            CP_COMMIT();
        }

        const uint32_t st = sb + ((kt & 1) ? 0u : 32768u);
        const uint32_t sKH = st, sVH = st + 16384;
        const int k0 = kt * KT;

        // ---- S = Q K^T  (2 MMAs per frag: (Qh+Ql)·Kh) ----
        float s[16][4];
        #pragma unroll
        for (int i = 0; i < 16; ++i)
            #pragma unroll
            for (int j = 0; j < 4; ++j) s[i][j] = 0.f;

        #pragma unroll
        for (int kp = 0; kp < 8; ++kp) {
            #pragma unroll
            for (int kd = 0; kd < 4; ++kd) {
                int g = lane >> 3, li = lane & 7;
                int row = kp * 16 + ((g >> 1) << 3) + li;
                int c = 2 * kd + (g & 1);
                uint32_t so = aswz(row, c);
                uint32_t kh4[4];
                ldsm_x4(kh4[0], kh4[1], kh4[2], kh4[3], sKH + so);
                mma2(s[2*kp],   qh[kd], kh4[0], kh4[1]);
                mma2(s[2*kp],   ql[kd], kh4[0], kh4[1]);
                mma2(s[2*kp+1], qh[kd], kh4[2], kh4[3]);
                mma2(s[2*kp+1], ql[kd], kh4[2], kh4[3]);
            }
        }

        // mask invalid keys (last tile)
        if (k0 + KT > SEQ) {
            #pragma unroll
            for (int kn = 0; kn < 16; ++kn) {
                int kg = k0 + kn * 8 + ((lane & 3) << 1);
                if (kg >= SEQ)     { s[kn][0] = -1e30f; s[kn][2] = -1e30f; }
                if (kg + 1 >= SEQ) { s[kn][1] = -1e30f; s[kn][3] = -1e30f; }
            }
        }

        // ---- online softmax ----
        float mx0 = -1e30f, mx1 = -1e30f;
        #pragma unroll
        for (int kn = 0; kn < 16; ++kn) {
            mx0 = fmaxf(mx0, fmaxf(s[kn][0], s[kn][1]));
            mx1 = fmaxf(mx1, fmaxf(s[kn][2], s[kn][3]));
        }
        mx0 = fmaxf(mx0, __shfl_xor_sync(0xffffffffu, mx0, 1));
        mx0 = fmaxf(mx0, __shfl_xor_sync(0xffffffffu, mx0, 2));
        mx1 = fmaxf(mx1, __shfl_xor_sync(0xffffffffu, mx1, 1));
        mx1 = fmaxf(mx1, __shfl_xor_sync(0xffffffffu, mx1, 2));
        float mn0 = fmaxf(m0, mx0), mn1 = fmaxf(m1, mx1);
        float c0 = __expf(m0 - mn0), c1 = __expf(m1 - mn1);
        float sum0 = 0.f, sum1 = 0.f;
        #pragma unroll
        for (int kn = 0; kn < 16; ++kn) {
            s[kn][0] = __expf(s[kn][0] - mn0);
            s[kn][1] = __expf(s[kn][1] - mn0);
            s[kn][2] = __expf(s[kn][2] - mn1);
            s[kn][3] = __expf(s[kn][3] - mn1);
            sum0 += s[kn][0] + s[kn][1];
            sum1 += s[kn][2] + s[kn][3];
        }
        sum0 += __shfl_xor_sync(0xffffffffu, sum0, 1);
        sum0 += __shfl_xor_sync(0xffffffffu, sum0, 2);
        sum1 += __shfl_xor_sync(0xffffffffu, sum1, 1);
        sum1 += __shfl_xor_sync(0xffffffffu, sum1, 2);
        l0 = l0 * c0 + sum0; l1 = l1 * c1 + sum1;
        m0 = mn0; m1 = mn1;
        #pragma unroll
        for (int nf = 0; nf < 8; ++nf) {
            o[nf][0] *= c0; o[nf][1] *= c0;
            o[nf][2] *= c1; o[nf][3] *= c1;
        }

        // ---- PV: O += (Ph+Pl) V ----
        #pragma unroll
        for (int kk = 0; kk < 8; ++kk) {
            uint32_t ph[4], pl[4];
            split2(s[2*kk][0],   s[2*kk][1],   ph[0], pl[0]);
            split2(s[2*kk][2],   s[2*kk][3],   ph[1], pl[1]);
            split2(s[2*kk+1][0], s[2*kk+1][1], ph[2], pl[2]);
            split2(s[2*kk+1][2], s[2*kk+1][3], ph[3], pl[3]);
            #pragma unroll
            for (int d16 = 0; d16 < 4; ++d16) {
                int g = lane >> 3, li = lane & 7;
                int row = kk * 16 + ((g & 1) << 3) + li;
                int c = d16 * 2 + (g >> 1);
                uint32_t so = aswz(row, c);
                uint32_t vh4[4];
                ldsm_x4_t(vh4[0], vh4[1], vh4[2], vh4[3], sVH + so);
                mma2(o[2*d16],   ph, vh4[0], vh4[1]);
                mma2(o[2*d16],   pl, vh4[0], vh4[1]);
                mma2(o[2*d16+1], ph, vh4[2], vh4[3]);
                mma2(o[2*d16+1], pl, vh4[2], vh4[3]);
            }
        }

        if (kt + 1 < NKT) {
            CP_WAIT0();        // next tile landed
            __syncthreads();   // this tile's reads done before it is refilled
        }
    }

    // ---- epilogue: o/l -> fp16 hi/lo into proj-A buffers ----
    float r0 = 1.f / l0, r1 = 1.f / l1;
    int rg = lane >> 2, t2 = (lane & 3) << 1;
    int row0 = q0 + w * 16 + rg, row1 = row0 + 8;
    #pragma unroll
    for (int nf = 0; nf < 8; ++nf) {
        int col = hh * DH + nf * 8 + t2;
        if (row0 < SEQ) {
            size_t gi = (size_t)(b * SEQ + row0) * CH + col;
            uint32_t hp, lp;
            split2(o[nf][0] * r0, o[nf][1] * r0, hp, lp);
            *(uint32_t*)(g_xh + gi) = hp;
            *(uint32_t*)(g_xl + gi) = lp;
        }
        if (row1 < SEQ) {
            size_t gi = (size_t)(b * SEQ + row1) * CH + col;
            uint32_t hp, lp;
            split2(o[nf][2] * r1, o[nf][3] * r1, hp, lp);
            *(uint32_t*)(g_xh + gi) = hp;
            *(uint32_t*)(g_xl + gi) = lp;
        }
    }
}

// ---------------------------------------------------------------------------
extern "C" void kernel_launch(void* const* d_in, const int* in_sizes, int n_in,
                              void* d_out, int out_size)
{
    const float* x      = (const float*)d_in[0];
    const float* qkv_w  = (const float*)d_in[1];
    const float* qkv_b  = (const float*)d_in[2];
    const float* proj_w = (const float*)d_in[3];
    const float* proj_b = (const float*)d_in[4];
    float* out = (float*)d_out;

    cudaFuncSetAttribute(attn_mma, cudaFuncAttributeMaxDynamicSharedMemorySize, ATT_SMEM);

    split_kernel<<<(MROWS*CH + 255)/256, 256>>>(x, 0, MROWS*CH);
    split_kernel<<<(QKV_N*CH + 255)/256, 256>>>(qkv_w, 1, QKV_N*CH);
    split_kernel<<<(CH*CH + 255)/256, 256>>>(proj_w, 2, CH*CH);

    mma_gemm<0><<<dim3(QKV_N/128, (MROWS + 127)/128), 128>>>(qkv_b, nullptr);

    attn_mma<<<dim3((SEQ + QT - 1)/QT, NH, BN), 256, ATT_SMEM>>>();

    mma_gemm<1><<<dim3(CH/128, (MROWS + 127)/128), 128>>>(proj_b, out);
}

// round 13
// speedup vs baseline: 2.7834x; 1.1441x over previous
#include <cuda_runtime.h>
#include <cuda_fp16.h>
#include <cstdint>

#define BN   32
#define SEQ  577
#define CH   768
#define NH   12
#define DH   64
#define MROWS (BN*SEQ)      /* 18464 */
#define QKV_N (3*CH)        /* 2304  */
#define QT   128
#define KT   128
#define NKT  5              /* ceil(577/128) */

// ---------------- scratch (__device__ globals; no allocs allowed) ----------
__device__ __half g_qh[BN*NH*SEQ*DH];                        // q single fp16 (scaled)
__device__ __half g_kh[BN*NH*SEQ*DH];                        // k single fp16
__device__ __half g_vh[BN*NH*SEQ*DH];                        // v single fp16
__device__ __half g_xh[MROWS*CH], g_xl[MROWS*CH];            // A hi/lo (x, then attn out)
__device__ __half g_wh[QKV_N*CH];                            // qkv_w single fp16
__device__ __half g_ph[CH*CH];                               // proj_w single fp16

// ---------------- helpers ---------------------------------------------------
__device__ __forceinline__ uint32_t smem_u32(const void* p) {
    uint32_t a;
    asm("{ .reg .u64 t; cvta.to.shared.u64 t, %1; cvt.u32.u64 %0, t; }" : "=r"(a) : "l"(p));
    return a;
}
__device__ __forceinline__ void cpa16(uint32_t dst, const void* src) {
    asm volatile("cp.async.cg.shared.global [%0], [%1], 16;" :: "r"(dst), "l"(src) : "memory");
}
#define CP_COMMIT() asm volatile("cp.async.commit_group;" ::: "memory")
#define CP_WAIT0()  asm volatile("cp.async.wait_group 0;" ::: "memory")

__device__ __forceinline__ void ldsm_x4(uint32_t& r0, uint32_t& r1,
                                        uint32_t& r2, uint32_t& r3, uint32_t addr) {
    asm volatile("ldmatrix.sync.aligned.m8n8.x4.shared.b16 {%0,%1,%2,%3}, [%4];"
                 : "=r"(r0), "=r"(r1), "=r"(r2), "=r"(r3) : "r"(addr));
}
__device__ __forceinline__ void ldsm_x4_t(uint32_t& r0, uint32_t& r1,
                                          uint32_t& r2, uint32_t& r3, uint32_t addr) {
    asm volatile("ldmatrix.sync.aligned.m8n8.x4.trans.shared.b16 {%0,%1,%2,%3}, [%4];"
                 : "=r"(r0), "=r"(r1), "=r"(r2), "=r"(r3) : "r"(addr));
}
__device__ __forceinline__ void mma16816(float* c, const uint32_t* a, const uint32_t* b) {
    asm volatile("mma.sync.aligned.m16n8k16.row.col.f32.f16.f16.f32 "
                 "{%0,%1,%2,%3}, {%4,%5,%6,%7}, {%8,%9}, {%0,%1,%2,%3};"
                 : "+f"(c[0]), "+f"(c[1]), "+f"(c[2]), "+f"(c[3])
                 : "r"(a[0]), "r"(a[1]), "r"(a[2]), "r"(a[3]), "r"(b[0]), "r"(b[1]));
}
__device__ __forceinline__ void mma2(float* c, const uint32_t* a, uint32_t b0, uint32_t b1) {
    asm volatile("mma.sync.aligned.m16n8k16.row.col.f32.f16.f16.f32 "
                 "{%0,%1,%2,%3}, {%4,%5,%6,%7}, {%8,%9}, {%0,%1,%2,%3};"
                 : "+f"(c[0]), "+f"(c[1]), "+f"(c[2]), "+f"(c[3])
                 : "r"(a[0]), "r"(a[1]), "r"(a[2]), "r"(a[3]), "r"(b0), "r"(b1));
}
// GEMM tile swizzle: 64B rows, 4 chunks
__device__ __forceinline__ uint32_t swoff(int r, int c) {
    return (uint32_t)(r * 64 + ((c ^ ((r >> 1) & 3)) << 4));
}
// attention tile swizzle: 128B rows, 8 chunks
__device__ __forceinline__ uint32_t aswz(int r, int c) {
    return (uint32_t)(r * 128 + ((c ^ (r & 7)) << 4));
}
// fp32 pair -> fp16 hi pair + fp16 lo pair (packed u32)
__device__ __forceinline__ void split2(float x, float y, uint32_t& hi, uint32_t& lo) {
    __half2 h2 = __floats2half2_rn(x, y);
    __half2 l2 = __floats2half2_rn(x - __half2float(__low2half(h2)),
                                   y - __half2float(__high2half(h2)));
    hi = reinterpret_cast<uint32_t&>(h2);
    lo = reinterpret_cast<uint32_t&>(l2);
}
__device__ __forceinline__ uint32_t pack2h(float x, float y) {
    __half2 h2 = __floats2half2_rn(x, y);
    return reinterpret_cast<uint32_t&>(h2);
}

// ---------------- split kernels ---------------------------------------------
__global__ void split_kernel(const float* __restrict__ src, int sel, int n) {
    int i = blockIdx.x * 256 + threadIdx.x;
    if (i >= n) return;
    float v = src[i];
    __half h = __float2half_rn(v);
    if (sel == 0) {
        g_xh[i] = h;
        g_xl[i] = __float2half_rn(v - __half2float(h));
    } else if (sel == 1) {
        g_wh[i] = h;
    } else {
        g_ph[i] = h;
    }
}

// ---------------- mma.sync fp16x2 GEMM, 64x64 warp tiles + cp.async ---------
// (unchanged from R11/R12, except q epilogue writes single fp16)
#define G_STG 24576

template<int MODE>
__global__ __launch_bounds__(128, 2) void mma_gemm(const float* __restrict__ bias,
                                                   float* __restrict__ out)
{
    __shared__ __align__(16) char smem[2 * G_STG];
    const uint32_t sb = smem_u32(smem);
    const int tid = threadIdx.x, lane = tid & 31, wid = tid >> 5;
    const int wm = wid & 1, wn = wid >> 1;          // 2 x 2 warp grid, 64x64 tiles
    const int tileN = blockIdx.x, tileM = blockIdx.y;

    const __half* __restrict__ Ah = g_xh;
    const __half* __restrict__ Al = g_xl;
    const __half* __restrict__ Bh = (MODE == 0) ? g_wh : g_ph;

    const uint32_t OFF_AH = 0, OFF_AL = 8192, OFF_BH = 16384;

    uint32_t lso[4]; size_t la[4], lb[4];
    #pragma unroll
    for (int i = 0; i < 4; ++i) {
        int slot = tid + (i << 7);
        int r = slot >> 2, c = slot & 3;
        lso[i] = swoff(r, c);
        int ga = tileM * 128 + r; if (ga > MROWS - 1) ga = MROWS - 1;
        la[i] = (size_t)ga * CH + c * 8;
        lb[i] = (size_t)(tileN * 128 + r) * CH + c * 8;
    }

    float acc[4][8][4];
    #pragma unroll
    for (int i = 0; i < 4; ++i)
        #pragma unroll
        for (int j = 0; j < 8; ++j)
            #pragma unroll
            for (int r = 0; r < 4; ++r) acc[i][j][r] = 0.f;

    {
        const uint32_t st = sb;
        #pragma unroll
        for (int i = 0; i < 4; ++i) {
            cpa16(st + OFF_AH + lso[i], Ah + la[i]);
            cpa16(st + OFF_AL + lso[i], Al + la[i]);
            cpa16(st + OFF_BH + lso[i], Bh + lb[i]);
        }
        CP_COMMIT();
    }

    for (int kc = 0; kc < 24; ++kc) {
        CP_WAIT0();
        __syncthreads();
        if (kc + 1 < 24) {
            const uint32_t st = sb + ((kc + 1) & 1) * G_STG;
            const size_t ko = (size_t)(kc + 1) * 32;
            #pragma unroll
            for (int i = 0; i < 4; ++i) {
                cpa16(st + OFF_AH + lso[i], Ah + la[i] + ko);
                cpa16(st + OFF_AL + lso[i], Al + la[i] + ko);
                cpa16(st + OFF_BH + lso[i], Bh + lb[i] + ko);
            }
            CP_COMMIT();
        }

        const uint32_t st = sb + (kc & 1) * G_STG;
        #pragma unroll
        for (int k16 = 0; k16 < 2; ++k16) {
            uint32_t ah[4][4], al[4][4];
            #pragma unroll
            for (int mf = 0; mf < 4; ++mf) {
                int row = wm * 64 + mf * 16 + (lane & 15);
                int c   = 2 * k16 + (lane >> 4);
                uint32_t o = swoff(row, c);
                ldsm_x4(ah[mf][0], ah[mf][1], ah[mf][2], ah[mf][3], st + OFF_AH + o);
                ldsm_x4(al[mf][0], al[mf][1], al[mf][2], al[mf][3], st + OFF_AL + o);
            }
            uint32_t bh[8][2];
            #pragma unroll
            for (int np = 0; np < 4; ++np) {
                int g = lane >> 3, l = lane & 7;
                int row = wn * 64 + np * 16 + (g >> 1) * 8 + l;
                int c   = 2 * k16 + (g & 1);
                uint32_t o = swoff(row, c);
                ldsm_x4(bh[np*2][0], bh[np*2][1], bh[np*2+1][0], bh[np*2+1][1],
                        st + OFF_BH + o);
            }
            #pragma unroll
            for (int mf = 0; mf < 4; ++mf)
                #pragma unroll
                for (int nf = 0; nf < 8; ++nf) {
                    mma16816(acc[mf][nf], ah[mf], bh[nf]);
                    mma16816(acc[mf][nf], al[mf], bh[nf]);
                }
        }
    }

    const int s = (MODE == 0) ? (tileN * 128) / CH : 0;
    const float scl = (MODE == 0 && s == 0) ? 0.125f : 1.0f;

    #pragma unroll
    for (int mf = 0; mf < 4; ++mf) {
        const int rbase = tileM * 128 + wm * 64 + mf * 16 + (lane >> 2);
        #pragma unroll
        for (int nf = 0; nf < 8; ++nf) {
            const int gcol = tileN * 128 + wn * 64 + nf * 8 + ((lane & 3) << 1);
            const float b0 = bias[gcol], b1 = bias[gcol + 1];
            #pragma unroll
            for (int hh = 0; hh < 2; ++hh) {
                const int row = rbase + hh * 8;
                if (row >= MROWS) continue;
                float v0 = (acc[mf][nf][hh*2+0] + b0) * scl;
                float v1 = (acc[mf][nf][hh*2+1] + b1) * scl;
                if (MODE == 0) {
                    int rem = gcol - s * CH;
                    int hd = rem >> 6, d = rem & 63;
                    int bb = row / SEQ, n = row - bb * SEQ;
                    size_t di = ((size_t)(bb * NH + hd) * SEQ + n) * DH + d;
                    __half* dst = (s == 0) ? g_qh : (s == 1) ? g_kh : g_vh;
                    *(uint32_t*)(dst + di) = pack2h(v0, v1);
                } else {
                    *(float2*)(out + (size_t)row * CH + gcol) = make_float2(v0, v1);
                }
            }
        }
    }
}

// ---------------- mma.sync flash attention, single-fp16 Q/K/P/V -------------
// smem 64KB: [0:16K) QH / stage1-KH, [16K:48K) stage0 (KH,VH),
//            [48K:64K) stage1-VH. Q region reused as stage1-KH after hoist.
#define ATT_SMEM 65536

__global__ __launch_bounds__(256) void attn_mma()
{
    extern __shared__ char sm[];
    const uint32_t sb = smem_u32(sm);
    const int tid = threadIdx.x, lane = tid & 31, w = tid >> 5;
    const int q0 = blockIdx.x * QT;
    const int hh = blockIdx.y, b = blockIdx.z;
    const size_t hb = (size_t)(b * NH + hh) * SEQ;

    // per-thread loader slots (128 rows x 8 chunks = 1024 slots, 4 per thread)
    int lr4[4], lc4[4]; uint32_t lso[4];
    #pragma unroll
    for (int p = 0; p < 4; ++p) {
        int slot = tid + (p << 8);
        lr4[p] = slot >> 3;
        lc4[p] = (slot & 7) * 8;
        lso[p] = aswz(slot >> 3, slot & 7);
    }

    // prologue: Q + KV tile 0 via cp.async
    #pragma unroll
    for (int p = 0; p < 4; ++p) {
        int gr = q0 + lr4[p]; if (gr > SEQ - 1) gr = SEQ - 1;
        size_t qi = ((hb + gr) << 6) + lc4[p];
        cpa16(sb + 0 + lso[p], g_qh + qi);
        int gk = lr4[p]; if (gk > SEQ - 1) gk = SEQ - 1;
        size_t ki = ((hb + gk) << 6) + lc4[p];
        cpa16(sb + 16384 + lso[p], g_kh + ki);
        cpa16(sb + 32768 + lso[p], g_vh + ki);
    }
    CP_COMMIT();
    CP_WAIT0();
    __syncthreads();

    // Q fragments -> registers (Q smem region is dead afterwards)
    uint32_t qh[4][4];
    #pragma unroll
    for (int kd = 0; kd < 4; ++kd) {
        int row = w * 16 + (lane & 15);
        int c = 2 * kd + (lane >> 4);
        uint32_t o = aswz(row, c);
        ldsm_x4(qh[kd][0], qh[kd][1], qh[kd][2], qh[kd][3], sb + 0 + o);
    }
    __syncthreads();   // all warps done reading Q before stage1 overwrites it

    float o[8][4];
    #pragma unroll
    for (int i = 0; i < 8; ++i)
        #pragma unroll
        for (int j = 0; j < 4; ++j) o[i][j] = 0.f;
    float m0 = -1e30f, m1 = -1e30f, l0 = 0.f, l1 = 0.f;

    for (int kt = 0; kt < NKT; ++kt) {
        // stage kt: even -> KH@16K,VH@32K ; odd -> KH@0,VH@48K
        if (kt + 1 < NKT) {
            const uint32_t nKH = ((kt + 1) & 1) ? (sb + 0u)     : (sb + 16384u);
            const uint32_t nVH = ((kt + 1) & 1) ? (sb + 49152u) : (sb + 32768u);
            const int k0n = (kt + 1) * KT;
            #pragma unroll
            for (int p = 0; p < 4; ++p) {
                int gk = k0n + lr4[p]; if (gk > SEQ - 1) gk = SEQ - 1;
                size_t ki = ((hb + gk) << 6) + lc4[p];
                cpa16(nKH + lso[p], g_kh + ki);
                cpa16(nVH + lso[p], g_vh + ki);
            }
            CP_COMMIT();
        }

        const uint32_t sKH = (kt & 1) ? (sb + 0u)     : (sb + 16384u);
        const uint32_t sVH = (kt & 1) ? (sb + 49152u) : (sb + 32768u);
        const int k0 = kt * KT;

        // ---- S = Q K^T  (single fp16 both sides) ----
        float s[16][4];
        #pragma unroll
        for (int i = 0; i < 16; ++i)
            #pragma unroll
            for (int j = 0; j < 4; ++j) s[i][j] = 0.f;

        #pragma unroll
        for (int kp = 0; kp < 8; ++kp) {
            #pragma unroll
            for (int kd = 0; kd < 4; ++kd) {
                int g = lane >> 3, li = lane & 7;
                int row = kp * 16 + ((g >> 1) << 3) + li;
                int c = 2 * kd + (g & 1);
                uint32_t so = aswz(row, c);
                uint32_t kh4[4];
                ldsm_x4(kh4[0], kh4[1], kh4[2], kh4[3], sKH + so);
                mma2(s[2*kp],   qh[kd], kh4[0], kh4[1]);
                mma2(s[2*kp+1], qh[kd], kh4[2], kh4[3]);
            }
        }

        // mask invalid keys (last tile)
        if (k0 + KT > SEQ) {
            #pragma unroll
            for (int kn = 0; kn < 16; ++kn) {
                int kg = k0 + kn * 8 + ((lane & 3) << 1);
                if (kg >= SEQ)     { s[kn][0] = -1e30f; s[kn][2] = -1e30f; }
                if (kg + 1 >= SEQ) { s[kn][1] = -1e30f; s[kn][3] = -1e30f; }
            }
        }

        // ---- online softmax ----
        float mx0 = -1e30f, mx1 = -1e30f;
        #pragma unroll
        for (int kn = 0; kn < 16; ++kn) {
            mx0 = fmaxf(mx0, fmaxf(s[kn][0], s[kn][1]));
            mx1 = fmaxf(mx1, fmaxf(s[kn][2], s[kn][3]));
        }
        mx0 = fmaxf(mx0, __shfl_xor_sync(0xffffffffu, mx0, 1));
        mx0 = fmaxf(mx0, __shfl_xor_sync(0xffffffffu, mx0, 2));
        mx1 = fmaxf(mx1, __shfl_xor_sync(0xffffffffu, mx1, 1));
        mx1 = fmaxf(mx1, __shfl_xor_sync(0xffffffffu, mx1, 2));
        float mn0 = fmaxf(m0, mx0), mn1 = fmaxf(m1, mx1);
        float c0 = __expf(m0 - mn0), c1 = __expf(m1 - mn1);
        float sum0 = 0.f, sum1 = 0.f;
        #pragma unroll
        for (int kn = 0; kn < 16; ++kn) {
            s[kn][0] = __expf(s[kn][0] - mn0);
            s[kn][1] = __expf(s[kn][1] - mn0);
            s[kn][2] = __expf(s[kn][2] - mn1);
            s[kn][3] = __expf(s[kn][3] - mn1);
            sum0 += s[kn][0] + s[kn][1];
            sum1 += s[kn][2] + s[kn][3];
        }
        sum0 += __shfl_xor_sync(0xffffffffu, sum0, 1);
        sum0 += __shfl_xor_sync(0xffffffffu, sum0, 2);
        sum1 += __shfl_xor_sync(0xffffffffu, sum1, 1);
        sum1 += __shfl_xor_sync(0xffffffffu, sum1, 2);
        l0 = l0 * c0 + sum0; l1 = l1 * c1 + sum1;
        m0 = mn0; m1 = mn1;
        #pragma unroll
        for (int nf = 0; nf < 8; ++nf) {
            o[nf][0] *= c0; o[nf][1] *= c0;
            o[nf][2] *= c1; o[nf][3] *= c1;
        }

        // ---- PV: O += P V  (P single fp16) ----
        #pragma unroll
        for (int kk = 0; kk < 8; ++kk) {
            uint32_t ph[4];
            ph[0] = pack2h(s[2*kk][0],   s[2*kk][1]);
            ph[1] = pack2h(s[2*kk][2],   s[2*kk][3]);
            ph[2] = pack2h(s[2*kk+1][0], s[2*kk+1][1]);
            ph[3] = pack2h(s[2*kk+1][2], s[2*kk+1][3]);
            #pragma unroll
            for (int d16 = 0; d16 < 4; ++d16) {
                int g = lane >> 3, li = lane & 7;
                int row = kk * 16 + ((g & 1) << 3) + li;
                int c = d16 * 2 + (g >> 1);
                uint32_t so = aswz(row, c);
                uint32_t vh4[4];
                ldsm_x4_t(vh4[0], vh4[1], vh4[2], vh4[3], sVH + so);
                mma2(o[2*d16],   ph, vh4[0], vh4[1]);
                mma2(o[2*d16+1], ph, vh4[2], vh4[3]);
            }
        }

        if (kt + 1 < NKT) {
            CP_WAIT0();        // next tile landed
            __syncthreads();   // this tile's reads done before it is refilled
        }
    }

    // ---- epilogue: o/l -> fp16 hi/lo into proj-A buffers ----
    float r0 = 1.f / l0, r1 = 1.f / l1;
    int rg = lane >> 2, t2 = (lane & 3) << 1;
    int row0 = q0 + w * 16 + rg, row1 = row0 + 8;
    #pragma unroll
    for (int nf = 0; nf < 8; ++nf) {
        int col = hh * DH + nf * 8 + t2;
        if (row0 < SEQ) {
            size_t gi = (size_t)(b * SEQ + row0) * CH + col;
            uint32_t hp, lp;
            split2(o[nf][0] * r0, o[nf][1] * r0, hp, lp);
            *(uint32_t*)(g_xh + gi) = hp;
            *(uint32_t*)(g_xl + gi) = lp;
        }
        if (row1 < SEQ) {
            size_t gi = (size_t)(b * SEQ + row1) * CH + col;
            uint32_t hp, lp;
            split2(o[nf][2] * r1, o[nf][3] * r1, hp, lp);
            *(uint32_t*)(g_xh + gi) = hp;
            *(uint32_t*)(g_xl + gi) = lp;
        }
    }
}

// ---------------------------------------------------------------------------
extern "C" void kernel_launch(void* const* d_in, const int* in_sizes, int n_in,
                              void* d_out, int out_size)
{
    const float* x      = (const float*)d_in[0];
    const float* qkv_w  = (const float*)d_in[1];
    const float* qkv_b  = (const float*)d_in[2];
    const float* proj_w = (const float*)d_in[3];
    const float* proj_b = (const float*)d_in[4];
    float* out = (float*)d_out;

    cudaFuncSetAttribute(attn_mma, cudaFuncAttributeMaxDynamicSharedMemorySize, ATT_SMEM);

    split_kernel<<<(MROWS*CH + 255)/256, 256>>>(x, 0, MROWS*CH);
    split_kernel<<<(QKV_N*CH + 255)/256, 256>>>(qkv_w, 1, QKV_N*CH);
    split_kernel<<<(CH*CH + 255)/256, 256>>>(proj_w, 2, CH*CH);

    mma_gemm<0><<<dim3(QKV_N/128, (MROWS + 127)/128), 128>>>(qkv_b, nullptr);

    attn_mma<<<dim3((SEQ + QT - 1)/QT, NH, BN), 256, ATT_SMEM>>>();

    mma_gemm<1><<<dim3(CH/128, (MROWS + 127)/128), 128>>>(proj_b, out);
}

// round 14
// speedup vs baseline: 3.8756x; 1.3924x over previous
#include <cuda_runtime.h>
#include <cuda_fp16.h>
#include <cstdint>

#define BN   32
#define SEQ  577
#define CH   768
#define NH   12
#define DH   64
#define MROWS (BN*SEQ)      /* 18464 */
#define QKV_N (3*CH)        /* 2304  */
#define QT   128
#define KT   128
#define NKT  5              /* ceil(577/128) */

// ---------------- scratch (__device__ globals; no allocs allowed) ----------
__device__ __half g_qh[BN*NH*SEQ*DH];                        // q fp16 (scaled)
__device__ __half g_kh[BN*NH*SEQ*DH];                        // k fp16
__device__ __half g_vh[BN*NH*SEQ*DH];                        // v fp16
__device__ __half g_xh[MROWS*CH];                            // A fp16 (x, then attn out)
__device__ __half g_wh[QKV_N*CH];                            // qkv_w fp16
__device__ __half g_ph[CH*CH];                               // proj_w fp16

// ---------------- helpers ---------------------------------------------------
__device__ __forceinline__ uint32_t smem_u32(const void* p) {
    uint32_t a;
    asm("{ .reg .u64 t; cvta.to.shared.u64 t, %1; cvt.u32.u64 %0, t; }" : "=r"(a) : "l"(p));
    return a;
}
__device__ __forceinline__ void cpa16(uint32_t dst, const void* src) {
    asm volatile("cp.async.cg.shared.global [%0], [%1], 16;" :: "r"(dst), "l"(src) : "memory");
}
#define CP_COMMIT() asm volatile("cp.async.commit_group;" ::: "memory")
#define CP_WAIT0()  asm volatile("cp.async.wait_group 0;" ::: "memory")

__device__ __forceinline__ void ldsm_x4(uint32_t& r0, uint32_t& r1,
                                        uint32_t& r2, uint32_t& r3, uint32_t addr) {
    asm volatile("ldmatrix.sync.aligned.m8n8.x4.shared.b16 {%0,%1,%2,%3}, [%4];"
                 : "=r"(r0), "=r"(r1), "=r"(r2), "=r"(r3) : "r"(addr));
}
__device__ __forceinline__ void ldsm_x4_t(uint32_t& r0, uint32_t& r1,
                                          uint32_t& r2, uint32_t& r3, uint32_t addr) {
    asm volatile("ldmatrix.sync.aligned.m8n8.x4.trans.shared.b16 {%0,%1,%2,%3}, [%4];"
                 : "=r"(r0), "=r"(r1), "=r"(r2), "=r"(r3) : "r"(addr));
}
__device__ __forceinline__ void mma16816(float* c, const uint32_t* a, const uint32_t* b) {
    asm volatile("mma.sync.aligned.m16n8k16.row.col.f32.f16.f16.f32 "
                 "{%0,%1,%2,%3}, {%4,%5,%6,%7}, {%8,%9}, {%0,%1,%2,%3};"
                 : "+f"(c[0]), "+f"(c[1]), "+f"(c[2]), "+f"(c[3])
                 : "r"(a[0]), "r"(a[1]), "r"(a[2]), "r"(a[3]), "r"(b[0]), "r"(b[1]));
}
__device__ __forceinline__ void mma2(float* c, const uint32_t* a, uint32_t b0, uint32_t b1) {
    asm volatile("mma.sync.aligned.m16n8k16.row.col.f32.f16.f16.f32 "
                 "{%0,%1,%2,%3}, {%4,%5,%6,%7}, {%8,%9}, {%0,%1,%2,%3};"
                 : "+f"(c[0]), "+f"(c[1]), "+f"(c[2]), "+f"(c[3])
                 : "r"(a[0]), "r"(a[1]), "r"(a[2]), "r"(a[3]), "r"(b0), "r"(b1));
}
// GEMM tile swizzle: 64B rows, 4 chunks
__device__ __forceinline__ uint32_t swoff(int r, int c) {
    return (uint32_t)(r * 64 + ((c ^ ((r >> 1) & 3)) << 4));
}
// attention tile swizzle: 128B rows, 8 chunks
__device__ __forceinline__ uint32_t aswz(int r, int c) {
    return (uint32_t)(r * 128 + ((c ^ (r & 7)) << 4));
}
__device__ __forceinline__ uint32_t pack2h(float x, float y) {
    __half2 h2 = __floats2half2_rn(x, y);
    return reinterpret_cast<uint32_t&>(h2);
}

// ---------------- convert kernels: fp32 -> fp16 ------------------------------
__global__ void split_kernel(const float* __restrict__ src, int sel, int n) {
    int i = blockIdx.x * 256 + threadIdx.x;
    if (i >= n) return;
    __half h = __float2half_rn(src[i]);
    if (sel == 0)      g_xh[i] = h;
    else if (sel == 1) g_wh[i] = h;
    else               g_ph[i] = h;
}

// ---------------- mma.sync fp16 GEMM, 64x64 warp tiles + cp.async ------------
// CTA 128x128, BK=32, 128 thr / 4 warps (2x2 grid of 64x64 warp tiles),
// 2-stage cp.async double buffer, ONE __syncthreads per K-chunk, 2 CTAs/SM.
// C = A*B (single fp16 both sides).
// MODE 0: A=x(fp16), B=qkv_w -> q (*0.125), k, v (+bias)
// MODE 1: A=attn-out(fp16), B=proj_w -> out (+bias)
#define G_STG 16384

template<int MODE>
__global__ __launch_bounds__(128, 2) void mma_gemm(const float* __restrict__ bias,
                                                   float* __restrict__ out)
{
    __shared__ __align__(16) char smem[2 * G_STG];
    const uint32_t sb = smem_u32(smem);
    const int tid = threadIdx.x, lane = tid & 31, wid = tid >> 5;
    const int wm = wid & 1, wn = wid >> 1;          // 2 x 2 warp grid, 64x64 tiles
    const int tileN = blockIdx.x, tileM = blockIdx.y;

    const __half* __restrict__ Ah = g_xh;
    const __half* __restrict__ Bh = (MODE == 0) ? g_wh : g_ph;

    const uint32_t OFF_AH = 0, OFF_BH = 8192;

    // loader: 128 rows x 4 chunks(16B) per buffer = 512 slots; 4 per thread
    uint32_t lso[4]; size_t la[4], lb[4];
    #pragma unroll
    for (int i = 0; i < 4; ++i) {
        int slot = tid + (i << 7);
        int r = slot >> 2, c = slot & 3;
        lso[i] = swoff(r, c);
        int ga = tileM * 128 + r; if (ga > MROWS - 1) ga = MROWS - 1;
        la[i] = (size_t)ga * CH + c * 8;
        lb[i] = (size_t)(tileN * 128 + r) * CH + c * 8;
    }

    float acc[4][8][4];
    #pragma unroll
    for (int i = 0; i < 4; ++i)
        #pragma unroll
        for (int j = 0; j < 8; ++j)
            #pragma unroll
            for (int r = 0; r < 4; ++r) acc[i][j][r] = 0.f;

    // prologue: stage 0 loads (chunk 0)
    {
        const uint32_t st = sb;
        #pragma unroll
        for (int i = 0; i < 4; ++i) {
            cpa16(st + OFF_AH + lso[i], Ah + la[i]);
            cpa16(st + OFF_BH + lso[i], Bh + lb[i]);
        }
        CP_COMMIT();
    }

    for (int kc = 0; kc < 24; ++kc) {
        CP_WAIT0();
        __syncthreads();
        if (kc + 1 < 24) {
            const uint32_t st = sb + ((kc + 1) & 1) * G_STG;
            const size_t ko = (size_t)(kc + 1) * 32;
            #pragma unroll
            for (int i = 0; i < 4; ++i) {
                cpa16(st + OFF_AH + lso[i], Ah + la[i] + ko);
                cpa16(st + OFF_BH + lso[i], Bh + lb[i] + ko);
            }
            CP_COMMIT();
        }

        const uint32_t st = sb + (kc & 1) * G_STG;
        #pragma unroll
        for (int k16 = 0; k16 < 2; ++k16) {
            uint32_t ah[4][4];
            #pragma unroll
            for (int mf = 0; mf < 4; ++mf) {
                int row = wm * 64 + mf * 16 + (lane & 15);
                int c   = 2 * k16 + (lane >> 4);
                uint32_t o = swoff(row, c);
                ldsm_x4(ah[mf][0], ah[mf][1], ah[mf][2], ah[mf][3], st + OFF_AH + o);
            }
            uint32_t bh[8][2];
            #pragma unroll
            for (int np = 0; np < 4; ++np) {
                int g = lane >> 3, l = lane & 7;
                int row = wn * 64 + np * 16 + (g >> 1) * 8 + l;
                int c   = 2 * k16 + (g & 1);
                uint32_t o = swoff(row, c);
                ldsm_x4(bh[np*2][0], bh[np*2][1], bh[np*2+1][0], bh[np*2+1][1],
                        st + OFF_BH + o);
            }
            #pragma unroll
            for (int mf = 0; mf < 4; ++mf)
                #pragma unroll
                for (int nf = 0; nf < 8; ++nf)
                    mma16816(acc[mf][nf], ah[mf], bh[nf]);
        }
    }

    // ---------------- epilogue ----------------
    const int s = (MODE == 0) ? (tileN * 128) / CH : 0;
    const float scl = (MODE == 0 && s == 0) ? 0.125f : 1.0f;

    #pragma unroll
    for (int mf = 0; mf < 4; ++mf) {
        const int rbase = tileM * 128 + wm * 64 + mf * 16 + (lane >> 2);
        #pragma unroll
        for (int nf = 0; nf < 8; ++nf) {
            const int gcol = tileN * 128 + wn * 64 + nf * 8 + ((lane & 3) << 1);
            const float b0 = bias[gcol], b1 = bias[gcol + 1];
            #pragma unroll
            for (int hh = 0; hh < 2; ++hh) {
                const int row = rbase + hh * 8;
                if (row >= MROWS) continue;
                float v0 = (acc[mf][nf][hh*2+0] + b0) * scl;
                float v1 = (acc[mf][nf][hh*2+1] + b1) * scl;
                if (MODE == 0) {
                    int rem = gcol - s * CH;
                    int hd = rem >> 6, d = rem & 63;
                    int bb = row / SEQ, n = row - bb * SEQ;
                    size_t di = ((size_t)(bb * NH + hd) * SEQ + n) * DH + d;
                    __half* dst = (s == 0) ? g_qh : (s == 1) ? g_kh : g_vh;
                    *(uint32_t*)(dst + di) = pack2h(v0, v1);
                } else {
                    *(float2*)(out + (size_t)row * CH + gcol) = make_float2(v0, v1);
                }
            }
        }
    }
}

// ---------------- mma.sync flash attention, single-fp16 (R13) ---------------
// smem 64KB: [0:16K) QH / stage1-KH, [16K:48K) stage0 (KH,VH),
//            [48K:64K) stage1-VH. Q region reused as stage1-KH after hoist.
#define ATT_SMEM 65536

__global__ __launch_bounds__(256) void attn_mma()
{
    extern __shared__ char sm[];
    const uint32_t sb = smem_u32(sm);
    const int tid = threadIdx.x, lane = tid & 31, w = tid >> 5;
    const int q0 = blockIdx.x * QT;
    const int hh = blockIdx.y, b = blockIdx.z;
    const size_t hb = (size_t)(b * NH + hh) * SEQ;

    int lr4[4], lc4[4]; uint32_t lso[4];
    #pragma unroll
    for (int p = 0; p < 4; ++p) {
        int slot = tid + (p << 8);
        lr4[p] = slot >> 3;
        lc4[p] = (slot & 7) * 8;
        lso[p] = aswz(slot >> 3, slot & 7);
    }

    // prologue: Q + KV tile 0 via cp.async
    #pragma unroll
    for (int p = 0; p < 4; ++p) {
        int gr = q0 + lr4[p]; if (gr > SEQ - 1) gr = SEQ - 1;
        size_t qi = ((hb + gr) << 6) + lc4[p];
        cpa16(sb + 0 + lso[p], g_qh + qi);
        int gk = lr4[p]; if (gk > SEQ - 1) gk = SEQ - 1;
        size_t ki = ((hb + gk) << 6) + lc4[p];
        cpa16(sb + 16384 + lso[p], g_kh + ki);
        cpa16(sb + 32768 + lso[p], g_vh + ki);
    }
    CP_COMMIT();
    CP_WAIT0();
    __syncthreads();

    // Q fragments -> registers
    uint32_t qh[4][4];
    #pragma unroll
    for (int kd = 0; kd < 4; ++kd) {
        int row = w * 16 + (lane & 15);
        int c = 2 * kd + (lane >> 4);
        uint32_t o = aswz(row, c);
        ldsm_x4(qh[kd][0], qh[kd][1], qh[kd][2], qh[kd][3], sb + 0 + o);
    }
    __syncthreads();

    float o[8][4];
    #pragma unroll
    for (int i = 0; i < 8; ++i)
        #pragma unroll
        for (int j = 0; j < 4; ++j) o[i][j] = 0.f;
    float m0 = -1e30f, m1 = -1e30f, l0 = 0.f, l1 = 0.f;

    for (int kt = 0; kt < NKT; ++kt) {
        if (kt + 1 < NKT) {
            const uint32_t nKH = ((kt + 1) & 1) ? (sb + 0u)     : (sb + 16384u);
            const uint32_t nVH = ((kt + 1) & 1) ? (sb + 49152u) : (sb + 32768u);
            const int k0n = (kt + 1) * KT;
            #pragma unroll
            for (int p = 0; p < 4; ++p) {
                int gk = k0n + lr4[p]; if (gk > SEQ - 1) gk = SEQ - 1;
                size_t ki = ((hb + gk) << 6) + lc4[p];
                cpa16(nKH + lso[p], g_kh + ki);
                cpa16(nVH + lso[p], g_vh + ki);
            }
            CP_COMMIT();
        }

        const uint32_t sKH = (kt & 1) ? (sb + 0u)     : (sb + 16384u);
        const uint32_t sVH = (kt & 1) ? (sb + 49152u) : (sb + 32768u);
        const int k0 = kt * KT;

        float s[16][4];
        #pragma unroll
        for (int i = 0; i < 16; ++i)
            #pragma unroll
            for (int j = 0; j < 4; ++j) s[i][j] = 0.f;

        #pragma unroll
        for (int kp = 0; kp < 8; ++kp) {
            #pragma unroll
            for (int kd = 0; kd < 4; ++kd) {
                int g = lane >> 3, li = lane & 7;
                int row = kp * 16 + ((g >> 1) << 3) + li;
                int c = 2 * kd + (g & 1);
                uint32_t so = aswz(row, c);
                uint32_t kh4[4];
                ldsm_x4(kh4[0], kh4[1], kh4[2], kh4[3], sKH + so);
                mma2(s[2*kp],   qh[kd], kh4[0], kh4[1]);
                mma2(s[2*kp+1], qh[kd], kh4[2], kh4[3]);
            }
        }

        if (k0 + KT > SEQ) {
            #pragma unroll
            for (int kn = 0; kn < 16; ++kn) {
                int kg = k0 + kn * 8 + ((lane & 3) << 1);
                if (kg >= SEQ)     { s[kn][0] = -1e30f; s[kn][2] = -1e30f; }
                if (kg + 1 >= SEQ) { s[kn][1] = -1e30f; s[kn][3] = -1e30f; }
            }
        }

        float mx0 = -1e30f, mx1 = -1e30f;
        #pragma unroll
        for (int kn = 0; kn < 16; ++kn) {
            mx0 = fmaxf(mx0, fmaxf(s[kn][0], s[kn][1]));
            mx1 = fmaxf(mx1, fmaxf(s[kn][2], s[kn][3]));
        }
        mx0 = fmaxf(mx0, __shfl_xor_sync(0xffffffffu, mx0, 1));
        mx0 = fmaxf(mx0, __shfl_xor_sync(0xffffffffu, mx0, 2));
        mx1 = fmaxf(mx1, __shfl_xor_sync(0xffffffffu, mx1, 1));
        mx1 = fmaxf(mx1, __shfl_xor_sync(0xffffffffu, mx1, 2));
        float mn0 = fmaxf(m0, mx0), mn1 = fmaxf(m1, mx1);
        float c0 = __expf(m0 - mn0), c1 = __expf(m1 - mn1);
        float sum0 = 0.f, sum1 = 0.f;
        #pragma unroll
        for (int kn = 0; kn < 16; ++kn) {
            s[kn][0] = __expf(s[kn][0] - mn0);
            s[kn][1] = __expf(s[kn][1] - mn0);
            s[kn][2] = __expf(s[kn][2] - mn1);
            s[kn][3] = __expf(s[kn][3] - mn1);
            sum0 += s[kn][0] + s[kn][1];
            sum1 += s[kn][2] + s[kn][3];
        }
        sum0 += __shfl_xor_sync(0xffffffffu, sum0, 1);
        sum0 += __shfl_xor_sync(0xffffffffu, sum0, 2);
        sum1 += __shfl_xor_sync(0xffffffffu, sum1, 1);
        sum1 += __shfl_xor_sync(0xffffffffu, sum1, 2);
        l0 = l0 * c0 + sum0; l1 = l1 * c1 + sum1;
        m0 = mn0; m1 = mn1;
        #pragma unroll
        for (int nf = 0; nf < 8; ++nf) {
            o[nf][0] *= c0; o[nf][1] *= c0;
            o[nf][2] *= c1; o[nf][3] *= c1;
        }

        #pragma unroll
        for (int kk = 0; kk < 8; ++kk) {
            uint32_t ph[4];
            ph[0] = pack2h(s[2*kk][0],   s[2*kk][1]);
            ph[1] = pack2h(s[2*kk][2],   s[2*kk][3]);
            ph[2] = pack2h(s[2*kk+1][0], s[2*kk+1][1]);
            ph[3] = pack2h(s[2*kk+1][2], s[2*kk+1][3]);
            #pragma unroll
            for (int d16 = 0; d16 < 4; ++d16) {
                int g = lane >> 3, li = lane & 7;
                int row = kk * 16 + ((g & 1) << 3) + li;
                int c = d16 * 2 + (g >> 1);
                uint32_t so = aswz(row, c);
                uint32_t vh4[4];
                ldsm_x4_t(vh4[0], vh4[1], vh4[2], vh4[3], sVH + so);
                mma2(o[2*d16],   ph, vh4[0], vh4[1]);
                mma2(o[2*d16+1], ph, vh4[2], vh4[3]);
            }
        }

        if (kt + 1 < NKT) {
            CP_WAIT0();
            __syncthreads();
        }
    }

    // ---- epilogue: o/l -> fp16 into proj-A buffer ----
    float r0 = 1.f / l0, r1 = 1.f / l1;
    int rg = lane >> 2, t2 = (lane & 3) << 1;
    int row0 = q0 + w * 16 + rg, row1 = row0 + 8;
    #pragma unroll
    for (int nf = 0; nf < 8; ++nf) {
        int col = hh * DH + nf * 8 + t2;
        if (row0 < SEQ) {
            size_t gi = (size_t)(b * SEQ + row0) * CH + col;
            *(uint32_t*)(g_xh + gi) = pack2h(o[nf][0] * r0, o[nf][1] * r0);
        }
        if (row1 < SEQ) {
            size_t gi = (size_t)(b * SEQ + row1) * CH + col;
            *(uint32_t*)(g_xh + gi) = pack2h(o[nf][2] * r1, o[nf][3] * r1);
        }
    }
}

// ---------------------------------------------------------------------------
extern "C" void kernel_launch(void* const* d_in, const int* in_sizes, int n_in,
                              void* d_out, int out_size)
{
    const float* x      = (const float*)d_in[0];
    const float* qkv_w  = (const float*)d_in[1];
    const float* qkv_b  = (const float*)d_in[2];
    const float* proj_w = (const float*)d_in[3];
    const float* proj_b = (const float*)d_in[4];
    float* out = (float*)d_out;

    cudaFuncSetAttribute(attn_mma, cudaFuncAttributeMaxDynamicSharedMemorySize, ATT_SMEM);

    split_kernel<<<(MROWS*CH + 255)/256, 256>>>(x, 0, MROWS*CH);
    split_kernel<<<(QKV_N*CH + 255)/256, 256>>>(qkv_w, 1, QKV_N*CH);
    split_kernel<<<(CH*CH + 255)/256, 256>>>(proj_w, 2, CH*CH);

    mma_gemm<0><<<dim3(QKV_N/128, (MROWS + 127)/128), 128>>>(qkv_b, nullptr);

    attn_mma<<<dim3((SEQ + QT - 1)/QT, NH, BN), 256, ATT_SMEM>>>();

    mma_gemm<1><<<dim3(CH/128, (MROWS + 127)/128), 128>>>(proj_b, out);
}

// round 15
// speedup vs baseline: 4.5078x; 1.1631x over previous
#include <cuda_runtime.h>
#include <cuda_fp16.h>
#include <cstdint>

#define BN   32
#define SEQ  577
#define CH   768
#define NH   12
#define DH   64
#define MROWS (BN*SEQ)      /* 18464 */
#define QKV_N (3*CH)        /* 2304  */
#define QT   128
#define KT   128
#define NKT  5              /* ceil(577/128) */

// q scale: DH^-0.5 * log2(e)  (softmax runs in exp2 domain)
#define QSCALE 0.180336879f

// ---------------- scratch (__device__ globals; no allocs allowed) ----------
__device__ __half g_qh[BN*NH*SEQ*DH];                        // q fp16 (scaled)
__device__ __half g_kh[BN*NH*SEQ*DH];                        // k fp16
__device__ __half g_vh[BN*NH*SEQ*DH];                        // v fp16
__device__ __half g_xh[MROWS*CH];                            // A fp16 (x, then attn out)
__device__ __half g_wh[QKV_N*CH];                            // qkv_w fp16
__device__ __half g_ph[CH*CH];                               // proj_w fp16

// ---------------- helpers ---------------------------------------------------
__device__ __forceinline__ uint32_t smem_u32(const void* p) {
    uint32_t a;
    asm("{ .reg .u64 t; cvta.to.shared.u64 t, %1; cvt.u32.u64 %0, t; }" : "=r"(a) : "l"(p));
    return a;
}
__device__ __forceinline__ void cpa16(uint32_t dst, const void* src) {
    asm volatile("cp.async.cg.shared.global [%0], [%1], 16;" :: "r"(dst), "l"(src) : "memory");
}
#define CP_COMMIT() asm volatile("cp.async.commit_group;" ::: "memory")
#define CP_WAIT0()  asm volatile("cp.async.wait_group 0;" ::: "memory")
#define CP_WAIT1()  asm volatile("cp.async.wait_group 1;" ::: "memory")

__device__ __forceinline__ void ldsm_x4(uint32_t& r0, uint32_t& r1,
                                        uint32_t& r2, uint32_t& r3, uint32_t addr) {
    asm volatile("ldmatrix.sync.aligned.m8n8.x4.shared.b16 {%0,%1,%2,%3}, [%4];"
                 : "=r"(r0), "=r"(r1), "=r"(r2), "=r"(r3) : "r"(addr));
}
__device__ __forceinline__ void ldsm_x4_t(uint32_t& r0, uint32_t& r1,
                                          uint32_t& r2, uint32_t& r3, uint32_t addr) {
    asm volatile("ldmatrix.sync.aligned.m8n8.x4.trans.shared.b16 {%0,%1,%2,%3}, [%4];"
                 : "=r"(r0), "=r"(r1), "=r"(r2), "=r"(r3) : "r"(addr));
}
__device__ __forceinline__ void mma16816(float* c, const uint32_t* a, const uint32_t* b) {
    asm volatile("mma.sync.aligned.m16n8k16.row.col.f32.f16.f16.f32 "
                 "{%0,%1,%2,%3}, {%4,%5,%6,%7}, {%8,%9}, {%0,%1,%2,%3};"
                 : "+f"(c[0]), "+f"(c[1]), "+f"(c[2]), "+f"(c[3])
                 : "r"(a[0]), "r"(a[1]), "r"(a[2]), "r"(a[3]), "r"(b[0]), "r"(b[1]));
}
__device__ __forceinline__ void mma2(float* c, const uint32_t* a, uint32_t b0, uint32_t b1) {
    asm volatile("mma.sync.aligned.m16n8k16.row.col.f32.f16.f16.f32 "
                 "{%0,%1,%2,%3}, {%4,%5,%6,%7}, {%8,%9}, {%0,%1,%2,%3};"
                 : "+f"(c[0]), "+f"(c[1]), "+f"(c[2]), "+f"(c[3])
                 : "r"(a[0]), "r"(a[1]), "r"(a[2]), "r"(a[3]), "r"(b0), "r"(b1));
}
// GEMM tile swizzle: 64B rows, 4 chunks
__device__ __forceinline__ uint32_t swoff(int r, int c) {
    return (uint32_t)(r * 64 + ((c ^ ((r >> 1) & 3)) << 4));
}
// attention tile swizzle: 128B rows, 8 chunks
__device__ __forceinline__ uint32_t aswz(int r, int c) {
    return (uint32_t)(r * 128 + ((c ^ (r & 7)) << 4));
}
__device__ __forceinline__ uint32_t pack2h(float x, float y) {
    __half2 h2 = __floats2half2_rn(x, y);
    return reinterpret_cast<uint32_t&>(h2);
}

// ---------------- fused vectorized fp32 -> fp16 convert ---------------------
#define N0_4 (MROWS*CH/4)
#define N1_4 (QKV_N*CH/4)
#define N2_4 (CH*CH/4)
__global__ void convert_all(const float* __restrict__ x,
                            const float* __restrict__ w,
                            const float* __restrict__ p) {
    int i = blockIdx.x * 256 + threadIdx.x;
    const float4* src; __half* dst; int j;
    if (i < N0_4)                 { src = (const float4*)x; dst = g_xh; j = i; }
    else if (i < N0_4 + N1_4)     { src = (const float4*)w; dst = g_wh; j = i - N0_4; }
    else if (i < N0_4+N1_4+N2_4)  { src = (const float4*)p; dst = g_ph; j = i - N0_4 - N1_4; }
    else return;
    float4 v = src[j];
    uint2 o;
    o.x = pack2h(v.x, v.y);
    o.y = pack2h(v.z, v.w);
    *(uint2*)(dst + (size_t)j * 4) = o;
}

// ---------------- mma.sync fp16 GEMM, 3-stage cp.async ----------------------
// CTA 128x128, BK=32, 128 thr / 4 warps (2x2 grid of 64x64 warp tiles),
// 3-stage cp.async, ONE __syncthreads per K-chunk, 2 CTAs/SM.
// MODE 0: A=x(fp16), B=qkv_w -> q (*QSCALE), k, v (+bias)
// MODE 1: A=attn-out(fp16), B=proj_w -> out (+bias)
#define G_STG 16384

template<int MODE>
__global__ __launch_bounds__(128, 2) void mma_gemm(const float* __restrict__ bias,
                                                   float* __restrict__ out)
{
    __shared__ __align__(16) char smem[3 * G_STG];   // 48KB static (2 CTA/SM)
    const uint32_t sb = smem_u32(smem);
    const int tid = threadIdx.x, lane = tid & 31, wid = tid >> 5;
    const int wm = wid & 1, wn = wid >> 1;
    const int tileN = blockIdx.x, tileM = blockIdx.y;

    const __half* __restrict__ Ah = g_xh;
    const __half* __restrict__ Bh = (MODE == 0) ? g_wh : g_ph;

    const uint32_t OFF_AH = 0, OFF_BH = 8192;

    uint32_t lso[4]; size_t la[4], lb[4];
    #pragma unroll
    for (int i = 0; i < 4; ++i) {
        int slot = tid + (i << 7);
        int r = slot >> 2, c = slot & 3;
        lso[i] = swoff(r, c);
        int ga = tileM * 128 + r; if (ga > MROWS - 1) ga = MROWS - 1;
        la[i] = (size_t)ga * CH + c * 8;
        lb[i] = (size_t)(tileN * 128 + r) * CH + c * 8;
    }

    float acc[4][8][4];
    #pragma unroll
    for (int i = 0; i < 4; ++i)
        #pragma unroll
        for (int j = 0; j < 8; ++j)
            #pragma unroll
            for (int r = 0; r < 4; ++r) acc[i][j][r] = 0.f;

    // prologue: chunks 0,1 into stages 0,1 (two commit groups)
    #pragma unroll
    for (int pc = 0; pc < 2; ++pc) {
        const uint32_t st = sb + pc * G_STG;
        const size_t ko = (size_t)pc * 32;
        #pragma unroll
        for (int i = 0; i < 4; ++i) {
            cpa16(st + OFF_AH + lso[i], Ah + la[i] + ko);
            cpa16(st + OFF_BH + lso[i], Bh + lb[i] + ko);
        }
        CP_COMMIT();
    }

    for (int kc = 0; kc < 24; ++kc) {
        if (kc < 23) { CP_WAIT1(); } else { CP_WAIT0(); }   // chunk kc landed
        __syncthreads();
        if (kc + 2 < 24) {                 // issue chunk kc+2 into stage (kc+2)%3
            const uint32_t st = sb + ((kc + 2) % 3) * G_STG;
            const size_t ko = (size_t)(kc + 2) * 32;
            #pragma unroll
            for (int i = 0; i < 4; ++i) {
                cpa16(st + OFF_AH + lso[i], Ah + la[i] + ko);
                cpa16(st + OFF_BH + lso[i], Bh + lb[i] + ko);
            }
            CP_COMMIT();
        }

        const uint32_t st = sb + (kc % 3) * G_STG;
        #pragma unroll
        for (int k16 = 0; k16 < 2; ++k16) {
            uint32_t ah[4][4];
            #pragma unroll
            for (int mf = 0; mf < 4; ++mf) {
                int row = wm * 64 + mf * 16 + (lane & 15);
                int c   = 2 * k16 + (lane >> 4);
                uint32_t o = swoff(row, c);
                ldsm_x4(ah[mf][0], ah[mf][1], ah[mf][2], ah[mf][3], st + OFF_AH + o);
            }
            uint32_t bh[8][2];
            #pragma unroll
            for (int np = 0; np < 4; ++np) {
                int g = lane >> 3, l = lane & 7;
                int row = wn * 64 + np * 16 + (g >> 1) * 8 + l;
                int c   = 2 * k16 + (g & 1);
                uint32_t o = swoff(row, c);
                ldsm_x4(bh[np*2][0], bh[np*2][1], bh[np*2+1][0], bh[np*2+1][1],
                        st + OFF_BH + o);
            }
            #pragma unroll
            for (int mf = 0; mf < 4; ++mf)
                #pragma unroll
                for (int nf = 0; nf < 8; ++nf)
                    mma16816(acc[mf][nf], ah[mf], bh[nf]);
        }
    }

    // ---------------- epilogue ----------------
    const int s = (MODE == 0) ? (tileN * 128) / CH : 0;
    const float scl = (MODE == 0 && s == 0) ? QSCALE : 1.0f;

    #pragma unroll
    for (int mf = 0; mf < 4; ++mf) {
        const int rbase = tileM * 128 + wm * 64 + mf * 16 + (lane >> 2);
        #pragma unroll
        for (int nf = 0; nf < 8; ++nf) {
            const int gcol = tileN * 128 + wn * 64 + nf * 8 + ((lane & 3) << 1);
            const float b0 = bias[gcol], b1 = bias[gcol + 1];
            #pragma unroll
            for (int hh = 0; hh < 2; ++hh) {
                const int row = rbase + hh * 8;
                if (row >= MROWS) continue;
                float v0 = (acc[mf][nf][hh*2+0] + b0) * scl;
                float v1 = (acc[mf][nf][hh*2+1] + b1) * scl;
                if (MODE == 0) {
                    int rem = gcol - s * CH;
                    int hd = rem >> 6, d = rem & 63;
                    int bb = row / SEQ, n = row - bb * SEQ;
                    size_t di = ((size_t)(bb * NH + hd) * SEQ + n) * DH + d;
                    __half* dst = (s == 0) ? g_qh : (s == 1) ? g_kh : g_vh;
                    *(uint32_t*)(dst + di) = pack2h(v0, v1);
                } else {
                    *(float2*)(out + (size_t)row * CH + gcol) = make_float2(v0, v1);
                }
            }
        }
    }
}

// ---------------- mma.sync flash attention (exp2 domain) --------------------
// smem 64KB: [0:16K) QH / stage1-KH, [16K:48K) stage0 (KH,VH),
//            [48K:64K) stage1-VH.
#define ATT_SMEM 65536

__global__ __launch_bounds__(256) void attn_mma()
{
    extern __shared__ char sm[];
    const uint32_t sb = smem_u32(sm);
    const int tid = threadIdx.x, lane = tid & 31, w = tid >> 5;
    const int q0 = blockIdx.x * QT;
    const int hh = blockIdx.y, b = blockIdx.z;
    const size_t hb = (size_t)(b * NH + hh) * SEQ;

    int lr4[4], lc4[4]; uint32_t lso[4];
    #pragma unroll
    for (int p = 0; p < 4; ++p) {
        int slot = tid + (p << 8);
        lr4[p] = slot >> 3;
        lc4[p] = (slot & 7) * 8;
        lso[p] = aswz(slot >> 3, slot & 7);
    }

    // prologue: Q + KV tile 0 via cp.async
    #pragma unroll
    for (int p = 0; p < 4; ++p) {
        int gr = q0 + lr4[p]; if (gr > SEQ - 1) gr = SEQ - 1;
        size_t qi = ((hb + gr) << 6) + lc4[p];
        cpa16(sb + 0 + lso[p], g_qh + qi);
        int gk = lr4[p]; if (gk > SEQ - 1) gk = SEQ - 1;
        size_t ki = ((hb + gk) << 6) + lc4[p];
        cpa16(sb + 16384 + lso[p], g_kh + ki);
        cpa16(sb + 32768 + lso[p], g_vh + ki);
    }
    CP_COMMIT();
    CP_WAIT0();
    __syncthreads();

    uint32_t qh[4][4];
    #pragma unroll
    for (int kd = 0; kd < 4; ++kd) {
        int row = w * 16 + (lane & 15);
        int c = 2 * kd + (lane >> 4);
        uint32_t o = aswz(row, c);
        ldsm_x4(qh[kd][0], qh[kd][1], qh[kd][2], qh[kd][3], sb + 0 + o);
    }
    __syncthreads();

    float o[8][4];
    #pragma unroll
    for (int i = 0; i < 8; ++i)
        #pragma unroll
        for (int j = 0; j < 4; ++j) o[i][j] = 0.f;
    float m0 = -1e30f, m1 = -1e30f, l0 = 0.f, l1 = 0.f;

    for (int kt = 0; kt < NKT; ++kt) {
        if (kt + 1 < NKT) {
            const uint32_t nKH = ((kt + 1) & 1) ? (sb + 0u)     : (sb + 16384u);
            const uint32_t nVH = ((kt + 1) & 1) ? (sb + 49152u) : (sb + 32768u);
            const int k0n = (kt + 1) * KT;
            #pragma unroll
            for (int p = 0; p < 4; ++p) {
                int gk = k0n + lr4[p]; if (gk > SEQ - 1) gk = SEQ - 1;
                size_t ki = ((hb + gk) << 6) + lc4[p];
                cpa16(nKH + lso[p], g_kh + ki);
                cpa16(nVH + lso[p], g_vh + ki);
            }
            CP_COMMIT();
        }

        const uint32_t sKH = (kt & 1) ? (sb + 0u)     : (sb + 16384u);
        const uint32_t sVH = (kt & 1) ? (sb + 49152u) : (sb + 32768u);
        const int k0 = kt * KT;

        float s[16][4];
        #pragma unroll
        for (int i = 0; i < 16; ++i)
            #pragma unroll
            for (int j = 0; j < 4; ++j) s[i][j] = 0.f;

        #pragma unroll
        for (int kp = 0; kp < 8; ++kp) {
            #pragma unroll
            for (int kd = 0; kd < 4; ++kd) {
                int g = lane >> 3, li = lane & 7;
                int row = kp * 16 + ((g >> 1) << 3) + li;
                int c = 2 * kd + (g & 1);
                uint32_t so = aswz(row, c);
                uint32_t kh4[4];
                ldsm_x4(kh4[0], kh4[1], kh4[2], kh4[3], sKH + so);
                mma2(s[2*kp],   qh[kd], kh4[0], kh4[1]);
                mma2(s[2*kp+1], qh[kd], kh4[2], kh4[3]);
            }
        }

        if (k0 + KT > SEQ) {
            #pragma unroll
            for (int kn = 0; kn < 16; ++kn) {
                int kg = k0 + kn * 8 + ((lane & 3) << 1);
                if (kg >= SEQ)     { s[kn][0] = -1e30f; s[kn][2] = -1e30f; }
                if (kg + 1 >= SEQ) { s[kn][1] = -1e30f; s[kn][3] = -1e30f; }
            }
        }

        // ---- online softmax in exp2 domain ----
        float mx0 = -1e30f, mx1 = -1e30f;
        #pragma unroll
        for (int kn = 0; kn < 16; ++kn) {
            mx0 = fmaxf(mx0, fmaxf(s[kn][0], s[kn][1]));
            mx1 = fmaxf(mx1, fmaxf(s[kn][2], s[kn][3]));
        }
        mx0 = fmaxf(mx0, __shfl_xor_sync(0xffffffffu, mx0, 1));
        mx0 = fmaxf(mx0, __shfl_xor_sync(0xffffffffu, mx0, 2));
        mx1 = fmaxf(mx1, __shfl_xor_sync(0xffffffffu, mx1, 1));
        mx1 = fmaxf(mx1, __shfl_xor_sync(0xffffffffu, mx1, 2));
        float mn0 = fmaxf(m0, mx0), mn1 = fmaxf(m1, mx1);
        float c0 = exp2f(m0 - mn0), c1 = exp2f(m1 - mn1);
        float sum0 = 0.f, sum1 = 0.f;
        #pragma unroll
        for (int kn = 0; kn < 16; ++kn) {
            s[kn][0] = exp2f(s[kn][0] - mn0);
            s[kn][1] = exp2f(s[kn][1] - mn0);
            s[kn][2] = exp2f(s[kn][2] - mn1);
            s[kn][3] = exp2f(s[kn][3] - mn1);
            sum0 += s[kn][0] + s[kn][1];
            sum1 += s[kn][2] + s[kn][3];
        }
        sum0 += __shfl_xor_sync(0xffffffffu, sum0, 1);
        sum0 += __shfl_xor_sync(0xffffffffu, sum0, 2);
        sum1 += __shfl_xor_sync(0xffffffffu, sum1, 1);
        sum1 += __shfl_xor_sync(0xffffffffu, sum1, 2);
        l0 = l0 * c0 + sum0; l1 = l1 * c1 + sum1;
        m0 = mn0; m1 = mn1;
        #pragma unroll
        for (int nf = 0; nf < 8; ++nf) {
            o[nf][0] *= c0; o[nf][1] *= c0;
            o[nf][2] *= c1; o[nf][3] *= c1;
        }

        #pragma unroll
        for (int kk = 0; kk < 8; ++kk) {
            uint32_t ph[4];
            ph[0] = pack2h(s[2*kk][0],   s[2*kk][1]);
            ph[1] = pack2h(s[2*kk][2],   s[2*kk][3]);
            ph[2] = pack2h(s[2*kk+1][0], s[2*kk+1][1]);
            ph[3] = pack2h(s[2*kk+1][2], s[2*kk+1][3]);
            #pragma unroll
            for (int d16 = 0; d16 < 4; ++d16) {
                int g = lane >> 3, li = lane & 7;
                int row = kk * 16 + ((g & 1) << 3) + li;
                int c = d16 * 2 + (g >> 1);
                uint32_t so = aswz(row, c);
                uint32_t vh4[4];
                ldsm_x4_t(vh4[0], vh4[1], vh4[2], vh4[3], sVH + so);
                mma2(o[2*d16],   ph, vh4[0], vh4[1]);
                mma2(o[2*d16+1], ph, vh4[2], vh4[3]);
            }
        }

        if (kt + 1 < NKT) {
            CP_WAIT0();
            __syncthreads();
        }
    }

    // ---- epilogue: o/l -> fp16 into proj-A buffer ----
    float r0 = 1.f / l0, r1 = 1.f / l1;
    int rg = lane >> 2, t2 = (lane & 3) << 1;
    int row0 = q0 + w * 16 + rg, row1 = row0 + 8;
    #pragma unroll
    for (int nf = 0; nf < 8; ++nf) {
        int col = hh * DH + nf * 8 + t2;
        if (row0 < SEQ) {
            size_t gi = (size_t)(b * SEQ + row0) * CH + col;
            *(uint32_t*)(g_xh + gi) = pack2h(o[nf][0] * r0, o[nf][1] * r0);
        }
        if (row1 < SEQ) {
            size_t gi = (size_t)(b * SEQ + row1) * CH + col;
            *(uint32_t*)(g_xh + gi) = pack2h(o[nf][2] * r1, o[nf][3] * r1);
        }
    }
}

// ---------------------------------------------------------------------------
extern "C" void kernel_launch(void* const* d_in, const int* in_sizes, int n_in,
                              void* d_out, int out_size)
{
    const float* x      = (const float*)d_in[0];
    const float* qkv_w  = (const float*)d_in[1];
    const float* qkv_b  = (const float*)d_in[2];
    const float* proj_w = (const float*)d_in[3];
    const float* proj_b = (const float*)d_in[4];
    float* out = (float*)d_out;

    cudaFuncSetAttribute(attn_mma, cudaFuncAttributeMaxDynamicSharedMemorySize, ATT_SMEM);

    const int NTOT4 = N0_4 + N1_4 + N2_4;
    convert_all<<<(NTOT4 + 255)/256, 256>>>(x, qkv_w, proj_w);

    mma_gemm<0><<<dim3(QKV_N/128, (MROWS + 127)/128), 128>>>(qkv_b, nullptr);

    attn_mma<<<dim3((SEQ + QT - 1)/QT, NH, BN), 256, ATT_SMEM>>>();

    mma_gemm<1><<<dim3(CH/128, (MROWS + 127)/128), 128>>>(proj_b, out);
}